// round 1
// baseline (speedup 1.0000x reference)
#include <cuda_runtime.h>
#include <cstdint>
#include <cstddef>

// ---------------------------------------------------------------------------
// EdgeConvEncoder: 3-layer EdgeConv GNN.
// Per layer:  T = X @ Wcomb (node tables, biases folded)   [GEMM phase]
//             per-edge softmax(q*k)*v*ew, red into ACC      [edge phase]
//             out = relu(ACC / max(cnt,1)) (+residual L2)   [finalize]
// ---------------------------------------------------------------------------

#define NN 50000

__device__ float g_T[NN * 768];      // node tables, max 6*O = 768 cols
__device__ float g_ACC[NN * 128];    // segment-sum accumulator
__device__ int   g_CNT[NN];          // per-node edge counts
__device__ float g_X0[NN * 128];     // layer-0 output (residual)
__device__ float g_H[NN * 64];       // layer-1 output
__device__ float g_W[128 * 768];     // combined weights (C x 6O)
__device__ float g_B[768];           // combined bias row (first 3O = bq|bk|bv)

// ---------------------------------------------------------------------------
// Build combined weight matrix:
// cols [0,O)=wq_top-wq_bot  [O,2O)=wk diff  [2O,3O)=wv diff
// cols [3O,4O)=wq_bot       [4O,5O)=wk_bot  [5O,6O)=wv_bot
// ---------------------------------------------------------------------------
__global__ void build_w_kernel(const float* __restrict__ wq, const float* __restrict__ wk,
                               const float* __restrict__ wv, const float* __restrict__ bq,
                               const float* __restrict__ bk, const float* __restrict__ bv,
                               int C, int O) {
    int M = 6 * O;
    int idx = blockIdx.x * blockDim.x + threadIdx.x;
    if (idx < C * M) {
        int c = idx / M;
        int m = idx - c * M;
        int which = m / O;
        int o = m - which * O;
        int qkv = which % 3;
        const float* w = (qkv == 0) ? wq : ((qkv == 1) ? wk : wv);
        float top = w[c * O + o];
        float bot = w[(C + c) * O + o];
        g_W[idx] = (which < 3) ? (top - bot) : bot;
    }
    if (idx < M) {
        int which = idx / O;
        int o = idx - which * O;
        float b = 0.f;
        if (which == 0) b = bq[o];
        else if (which == 1) b = bk[o];
        else if (which == 2) b = bv[o];
        g_B[idx] = b;
    }
}

// ---------------------------------------------------------------------------
// fp32 SIMT GEMM: g_T[N x M] = A[N x K] @ g_W[K x M] + g_B
// BM=128, BN=64, BK=16, 256 threads, 8x4 microtile.
// ---------------------------------------------------------------------------
__global__ __launch_bounds__(256) void gemm_kernel(const float* __restrict__ A,
                                                   int N, int K, int M) {
    __shared__ float As[16][136];   // transposed [k][row], padded
    __shared__ float Bs[16][68];    // [k][col], padded

    int tid = threadIdx.x;
    int tx = tid & 15;
    int ty = tid >> 4;
    int row0 = blockIdx.y * 128;
    int col0 = blockIdx.x * 64;

    int arow = tid >> 1;           // 0..127
    int ak   = (tid & 1) << 3;     // 0 or 8
    int brow = tid >> 4;           // 0..15
    int bcol = (tid & 15) << 2;    // 0..60

    float acc[8][4];
#pragma unroll
    for (int i = 0; i < 8; i++)
#pragma unroll
        for (int j = 0; j < 4; j++) acc[i][j] = 0.f;

    for (int k0 = 0; k0 < K; k0 += 16) {
        int r = row0 + arow;
        float4 a0 = make_float4(0.f, 0.f, 0.f, 0.f);
        float4 a1 = make_float4(0.f, 0.f, 0.f, 0.f);
        if (r < N) {
            const float* ap = A + (size_t)r * K + k0 + ak;
            a0 = *(const float4*)(ap);
            a1 = *(const float4*)(ap + 4);
        }
        As[ak + 0][arow] = a0.x; As[ak + 1][arow] = a0.y;
        As[ak + 2][arow] = a0.z; As[ak + 3][arow] = a0.w;
        As[ak + 4][arow] = a1.x; As[ak + 5][arow] = a1.y;
        As[ak + 6][arow] = a1.z; As[ak + 7][arow] = a1.w;
        float4 bvv = *(const float4*)(g_W + (size_t)(k0 + brow) * M + col0 + bcol);
        *(float4*)(&Bs[brow][bcol]) = bvv;
        __syncthreads();
#pragma unroll
        for (int kk = 0; kk < 16; kk++) {
            float4 af0 = *(const float4*)(&As[kk][ty << 3]);
            float4 af1 = *(const float4*)(&As[kk][(ty << 3) + 4]);
            float4 bf  = *(const float4*)(&Bs[kk][tx << 2]);
            float a[8] = {af0.x, af0.y, af0.z, af0.w, af1.x, af1.y, af1.z, af1.w};
            float b[4] = {bf.x, bf.y, bf.z, bf.w};
#pragma unroll
            for (int i = 0; i < 8; i++)
#pragma unroll
                for (int j = 0; j < 4; j++)
                    acc[i][j] = fmaf(a[i], b[j], acc[i][j]);
        }
        __syncthreads();
    }

    float4 bias = *(const float4*)(&g_B[col0 + (tx << 2)]);
#pragma unroll
    for (int i = 0; i < 8; i++) {
        int r = row0 + (ty << 3) + i;
        if (r < N) {
            float4 o;
            o.x = acc[i][0] + bias.x;
            o.y = acc[i][1] + bias.y;
            o.z = acc[i][2] + bias.z;
            o.w = acc[i][3] + bias.w;
            *(float4*)(g_T + (size_t)r * M + col0 + (tx << 2)) = o;
        }
    }
}

// ---------------------------------------------------------------------------
__global__ void zero_kernel(int nAcc) {
    int i = blockIdx.x * blockDim.x + threadIdx.x;
    if (i < nAcc) g_ACC[i] = 0.f;
    if (i < NN) g_CNT[i] = 0;
}

// ---------------------------------------------------------------------------
// Edge kernel: one warp per edge. T row layout per node:
//   [0,O)=q_dst  [O,2O)=k_dst  [2O,3O)=v_dst  [3O,4O)=q_src ... [5O,6O)=v_src
// q = qd[dst] + qs[src]  (biases already folded into dst half)
// softmax over HS-channel groups (HS/V = 4 lanes per group -> xor 1,2 bfly)
// ---------------------------------------------------------------------------
template <int O, int HS>
__global__ __launch_bounds__(256) void edge_kernel(const int* __restrict__ e, int E) {
    int gw = (blockIdx.x * 256 + threadIdx.x) >> 5;
    if (gw >= E) return;
    int lane = threadIdx.x & 31;
    int src = e[gw];
    int dst = e[E + gw];

    constexpr int V = O / 32;         // floats per lane (4 or 2)
    constexpr int STRIDE = 6 * O;
    const float* D = g_T + (size_t)dst * STRIDE;
    const float* S = g_T + (size_t)src * STRIDE + 3 * O;
    int base = lane * V;

    float dq[V], sq[V], dk[V], sk[V], dv[V], sv[V];
    if constexpr (V == 4) {
        *(float4*)dq = *(const float4*)(D + base);
        *(float4*)dk = *(const float4*)(D + O + base);
        *(float4*)dv = *(const float4*)(D + 2 * O + base);
        *(float4*)sq = *(const float4*)(S + base);
        *(float4*)sk = *(const float4*)(S + O + base);
        *(float4*)sv = *(const float4*)(S + 2 * O + base);
    } else {
        *(float2*)dq = *(const float2*)(D + base);
        *(float2*)dk = *(const float2*)(D + O + base);
        *(float2*)dv = *(const float2*)(D + 2 * O + base);
        *(float2*)sq = *(const float2*)(S + base);
        *(float2*)sk = *(const float2*)(S + O + base);
        *(float2*)sv = *(const float2*)(S + 2 * O + base);
    }

    // ew = sign(log|dst-src| - log 8): -1 if d<8 (incl d=0 -> log0=-inf), 0 if d==8, +1 if d>8
    int dd = dst - src;
    if (dd < 0) dd = -dd;
    float ew = (dd > 8) ? 1.0f : ((dd == 8) ? 0.0f : -1.0f);

    const float scale = (HS == 16) ? 0.25f : 0.35355339059327373f;  // 1/sqrt(HS)
    float t[V];
    float m = -1e30f;
#pragma unroll
    for (int u = 0; u < V; u++) {
        t[u] = (dq[u] + sq[u]) * (dk[u] + sk[u]) * scale;
        m = fmaxf(m, t[u]);
    }
    m = fmaxf(m, __shfl_xor_sync(0xffffffffu, m, 1));
    m = fmaxf(m, __shfl_xor_sync(0xffffffffu, m, 2));
    float p[V];
    float ssum = 0.f;
#pragma unroll
    for (int u = 0; u < V; u++) {
        p[u] = __expf(t[u] - m);
        ssum += p[u];
    }
    ssum += __shfl_xor_sync(0xffffffffu, ssum, 1);
    ssum += __shfl_xor_sync(0xffffffffu, ssum, 2);
    float inv = 1.0f / ssum;

    float ctx[V];
#pragma unroll
    for (int u = 0; u < V; u++)
        ctx[u] = p[u] * inv * (dv[u] + sv[u]) * ew;

    float* outp = g_ACC + (size_t)dst * O + base;
    if constexpr (V == 4) {
        asm volatile("red.global.add.v4.f32 [%0], {%1, %2, %3, %4};"
                     :: "l"(outp), "f"(ctx[0]), "f"(ctx[1]), "f"(ctx[2]), "f"(ctx[3])
                     : "memory");
    } else {
        asm volatile("red.global.add.v2.f32 [%0], {%1, %2};"
                     :: "l"(outp), "f"(ctx[0]), "f"(ctx[1])
                     : "memory");
    }
    if (lane == 0) atomicAdd(&g_CNT[dst], 1);
}

// ---------------------------------------------------------------------------
__global__ void finalize_relu_kernel(float* __restrict__ out, int N, int O) {
    int i = blockIdx.x * blockDim.x + threadIdx.x;
    if (i >= N * O) return;
    int n = i / O;
    int c = g_CNT[n];
    float cf = (float)(c > 0 ? c : 1);
    out[i] = fmaxf(g_ACC[i] / cf, 0.f);
}

__global__ void finalize_res_kernel(float* __restrict__ out, int N, int O) {
    int i = blockIdx.x * blockDim.x + threadIdx.x;
    if (i >= N * O) return;
    int n = i / O;
    int c = g_CNT[n];
    float cf = (float)(c > 0 ? c : 1);
    out[i] = fmaxf(g_ACC[i] / cf + g_X0[i], 0.f);
}

// ---------------------------------------------------------------------------
extern "C" void kernel_launch(void* const* d_in, const int* in_sizes, int n_in,
                              void* d_out, int out_size) {
    const float* x   = (const float*)d_in[0];
    const int*   e0  = (const int*)d_in[1];
    const int*   e1  = (const int*)d_in[2];
    const int*   e2  = (const int*)d_in[3];
    // d_in[4] = batch (unused)
    const float* wq0 = (const float*)d_in[5],  *bq0 = (const float*)d_in[6];
    const float* wk0 = (const float*)d_in[7],  *bk0 = (const float*)d_in[8];
    const float* wv0 = (const float*)d_in[9],  *bv0 = (const float*)d_in[10];
    const float* wq1 = (const float*)d_in[11], *bq1 = (const float*)d_in[12];
    const float* wk1 = (const float*)d_in[13], *bk1 = (const float*)d_in[14];
    const float* wv1 = (const float*)d_in[15], *bv1 = (const float*)d_in[16];
    const float* wq2 = (const float*)d_in[17], *bq2 = (const float*)d_in[18];
    const float* wk2 = (const float*)d_in[19], *bk2 = (const float*)d_in[20];
    const float* wv2 = (const float*)d_in[21], *bv2 = (const float*)d_in[22];
    float* out = (float*)d_out;

    int N  = in_sizes[0] / 128;   // 50000
    int E0 = in_sizes[1] / 2;
    int E1 = in_sizes[2] / 2;
    int E2 = in_sizes[3] / 2;

    float *pX0 = nullptr, *pH = nullptr;
    cudaGetSymbolAddress((void**)&pX0, g_X0);
    cudaGetSymbolAddress((void**)&pH, g_H);

    // ---- Layer 0: C=128, O=128 ----
    {
        const int C = 128, O = 128, M = 6 * O;
        build_w_kernel<<<(C * M + 255) / 256, 256>>>(wq0, wk0, wv0, bq0, bk0, bv0, C, O);
        dim3 grid(M / 64, (N + 127) / 128);
        gemm_kernel<<<grid, 256>>>(x, N, C, M);
        zero_kernel<<<(N * O + 255) / 256, 256>>>(N * O);
        edge_kernel<128, 16><<<(E0 + 7) / 8, 256>>>(e0, E0);
        finalize_relu_kernel<<<(N * O + 255) / 256, 256>>>(pX0, N, O);
    }
    // ---- Layer 1: C=128, O=64 ----
    {
        const int C = 128, O = 64, M = 6 * O;
        build_w_kernel<<<(C * M + 255) / 256, 256>>>(wq1, wk1, wv1, bq1, bk1, bv1, C, O);
        dim3 grid(M / 64, (N + 127) / 128);
        gemm_kernel<<<grid, 256>>>(pX0, N, C, M);
        zero_kernel<<<(N * O + 255) / 256, 256>>>(N * O);
        edge_kernel<64, 8><<<(E1 + 7) / 8, 256>>>(e1, E1);
        finalize_relu_kernel<<<(N * O + 255) / 256, 256>>>(pH, N, O);
    }
    // ---- Layer 2: C=64, O=128 ----
    {
        const int C = 64, O = 128, M = 6 * O;
        build_w_kernel<<<(C * M + 255) / 256, 256>>>(wq2, wk2, wv2, bq2, bk2, bv2, C, O);
        dim3 grid(M / 64, (N + 127) / 128);
        gemm_kernel<<<grid, 256>>>(pH, N, C, M);
        zero_kernel<<<(N * O + 255) / 256, 256>>>(N * O);
        edge_kernel<128, 16><<<(E2 + 7) / 8, 256>>>(e2, E2);
        finalize_res_kernel<<<(N * O + 255) / 256, 256>>>(out, N, O);
    }
}

// round 3
// speedup vs baseline: 1.8741x; 1.8741x over previous
#include <cuda_runtime.h>
#include <cuda_fp16.h>
#include <cstdint>
#include <cstddef>

// ---------------------------------------------------------------------------
// EdgeConvEncoder: 3-layer EdgeConv GNN.
// Per layer:  T = X @ Wcomb  (fp16 tensor-core GEMM, fp32 accum, fp16 out)
//             per-edge softmax(q*k)*v*ew, red into fp32 ACC
//             out = relu(ACC / max(cnt,1)) (+residual on layer 2)
// ---------------------------------------------------------------------------

#define NN 50000

__device__ __half g_T[NN * 768];     // node tables (fp16), max 6*O = 768 cols
__device__ float  g_ACC[NN * 128];   // segment-sum accumulator
__device__ int    g_CNT[NN];         // per-node edge counts
__device__ float  g_X0[NN * 128];    // layer-0 output (residual)
__device__ float  g_H[NN * 64];      // layer-1 output
__device__ __half g_W[128 * 768];    // combined weights (C x 6O), fp16
__device__ float  g_B[768];          // combined bias row (first 3O = bq|bk|bv)

// ---------------------------------------------------------------------------
// Build combined fp16 weight matrix:
// cols [0,O)=wq_top-wq_bot  [O,2O)=wk diff  [2O,3O)=wv diff
// cols [3O,4O)=wq_bot       [4O,5O)=wk_bot  [5O,6O)=wv_bot
// ---------------------------------------------------------------------------
__global__ void build_w_kernel(const float* __restrict__ wq, const float* __restrict__ wk,
                               const float* __restrict__ wv, const float* __restrict__ bq,
                               const float* __restrict__ bk, const float* __restrict__ bv,
                               int C, int O) {
    int M = 6 * O;
    int idx = blockIdx.x * blockDim.x + threadIdx.x;
    if (idx < C * M) {
        int c = idx / M;
        int m = idx - c * M;
        int which = m / O;
        int o = m - which * O;
        int qkv = which % 3;
        const float* w = (qkv == 0) ? wq : ((qkv == 1) ? wk : wv);
        float top = w[c * O + o];
        float bot = w[(C + c) * O + o];
        g_W[idx] = __float2half((which < 3) ? (top - bot) : bot);
    }
    if (idx < M) {
        int which = idx / O;
        int o = idx - which * O;
        float b = 0.f;
        if (which == 0) b = bq[o];
        else if (which == 1) b = bk[o];
        else if (which == 2) b = bv[o];
        g_B[idx] = b;
    }
}

// ---------------------------------------------------------------------------
// fp16 tensor-core GEMM: g_T[N x M](fp16) = A[N x K](fp32) @ g_W[K x M](fp16) + g_B
// BM=128, BN=64, BK=64, 256 threads (8 warps, 4x2), mma.m16n8k16.
// ---------------------------------------------------------------------------
__device__ __forceinline__ uint32_t smem_u32(const void* p) {
    return (uint32_t)__cvta_generic_to_shared(p);
}

__global__ __launch_bounds__(256) void gemm_hmma_kernel(const float* __restrict__ A,
                                                        int N, int K, int M) {
    constexpr int AS = 72;  // A smem row stride (halfs), 144B
    constexpr int BS = 72;  // B smem row stride (halfs)
    __shared__ __align__(16) __half Asm[128 * AS];   // [row][k], 18.4KB
    __shared__ __align__(16) __half Bsm[64 * BS];    // [k][n],   9.2KB

    int tid  = threadIdx.x;
    int wid  = tid >> 5;
    int lane = tid & 31;
    int warp_m = wid >> 1;   // 0..3  -> 32 rows each
    int warp_n = wid & 1;    // 0..1  -> 32 cols each
    int row0 = blockIdx.y * 128;
    int col0 = blockIdx.x * 64;

    float acc[2][4][4];
#pragma unroll
    for (int mt = 0; mt < 2; mt++)
#pragma unroll
        for (int nt = 0; nt < 4; nt++)
#pragma unroll
            for (int i = 0; i < 4; i++) acc[mt][nt][i] = 0.f;

    for (int k0 = 0; k0 < K; k0 += 64) {
        // ---- load A tile: 128 rows x 64 k, fp32 -> fp16 ----
#pragma unroll
        for (int t = 0; t < 8; t++) {
            int idx = tid + t * 256;            // 0..2047
            int r   = idx >> 4;                 // 0..127
            int c   = (idx & 15) << 2;          // 0..60
            float4 v = make_float4(0.f, 0.f, 0.f, 0.f);
            if (row0 + r < N)
                v = *(const float4*)(A + (size_t)(row0 + r) * K + k0 + c);
            __half h[4];
            h[0] = __float2half(v.x); h[1] = __float2half(v.y);
            h[2] = __float2half(v.z); h[3] = __float2half(v.w);
            *(uint2*)(&Asm[r * AS + c]) = *(uint2*)h;
        }
        // ---- load B tile: 64 k x 64 n, fp16 ----
#pragma unroll
        for (int t = 0; t < 2; t++) {
            int idx = tid + t * 256;            // 0..511
            int r   = idx >> 3;                 // 0..63
            int c   = (idx & 7) << 3;           // 0..56
            uint4 v = *(const uint4*)(g_W + (size_t)(k0 + r) * M + col0 + c);
            *(uint4*)(&Bsm[r * BS + c]) = v;
        }
        __syncthreads();

        int m0 = warp_m * 32;
        int n0 = warp_n * 32;
#pragma unroll
        for (int kk = 0; kk < 64; kk += 16) {
            uint32_t a[2][4];
#pragma unroll
            for (int mt = 0; mt < 2; mt++) {
                uint32_t addr = smem_u32(&Asm[(m0 + mt * 16 + (lane & 15)) * AS +
                                              kk + (lane >> 4) * 8]);
                asm volatile("ldmatrix.sync.aligned.m8n8.x4.shared.b16 {%0,%1,%2,%3}, [%4];"
                             : "=r"(a[mt][0]), "=r"(a[mt][1]), "=r"(a[mt][2]), "=r"(a[mt][3])
                             : "r"(addr));
            }
            uint32_t b[4][2];
#pragma unroll
            for (int np = 0; np < 2; np++) {  // pairs of n-tiles
                uint32_t addr = smem_u32(&Bsm[(kk + (lane & 15)) * BS +
                                              n0 + np * 16 + (lane >> 4) * 8]);
                uint32_t r0, r1, r2, r3;
                asm volatile("ldmatrix.sync.aligned.m8n8.x4.trans.shared.b16 {%0,%1,%2,%3}, [%4];"
                             : "=r"(r0), "=r"(r1), "=r"(r2), "=r"(r3)
                             : "r"(addr));
                b[np * 2 + 0][0] = r0; b[np * 2 + 0][1] = r1;
                b[np * 2 + 1][0] = r2; b[np * 2 + 1][1] = r3;
            }
#pragma unroll
            for (int mt = 0; mt < 2; mt++)
#pragma unroll
                for (int nt = 0; nt < 4; nt++) {
                    asm volatile(
                        "mma.sync.aligned.m16n8k16.row.col.f32.f16.f16.f32 "
                        "{%0,%1,%2,%3}, {%4,%5,%6,%7}, {%8,%9}, {%0,%1,%2,%3};"
                        : "+f"(acc[mt][nt][0]), "+f"(acc[mt][nt][1]),
                          "+f"(acc[mt][nt][2]), "+f"(acc[mt][nt][3])
                        : "r"(a[mt][0]), "r"(a[mt][1]), "r"(a[mt][2]), "r"(a[mt][3]),
                          "r"(b[nt][0]), "r"(b[nt][1]));
                }
        }
        __syncthreads();
    }

    // ---- epilogue: + bias, fp16 store ----
    int g   = lane >> 2;        // group row 0..7
    int t4  = lane & 3;         // col pair 0..3
#pragma unroll
    for (int mt = 0; mt < 2; mt++) {
#pragma unroll
        for (int nt = 0; nt < 4; nt++) {
            int col = col0 + warp_n * 32 + nt * 8 + t4 * 2;
            float bx = g_B[col], by = g_B[col + 1];
#pragma unroll
            for (int h = 0; h < 2; h++) {
                int r = row0 + warp_m * 32 + mt * 16 + g + h * 8;
                if (r < N) {
                    __half2 o = __floats2half2_rn(acc[mt][nt][h * 2 + 0] + bx,
                                                  acc[mt][nt][h * 2 + 1] + by);
                    *(__half2*)(g_T + (size_t)r * M + col) = o;
                }
            }
        }
    }
}

// ---------------------------------------------------------------------------
__global__ void zero_kernel(int nAcc) {
    int i = blockIdx.x * blockDim.x + threadIdx.x;
    if (i < nAcc) g_ACC[i] = 0.f;
    if (i < NN) g_CNT[i] = 0;
}

// ---------------------------------------------------------------------------
// Edge kernel: one warp per edge. T row (fp16) layout per node:
//   [0,O)=q_dst [O,2O)=k_dst [2O,3O)=v_dst [3O,4O)=q_src [4O,5O)=k_src [5O,6O)=v_src
// softmax over HS channels (HS/V = 4 lanes per group -> xor 1,2 bfly)
// ---------------------------------------------------------------------------
template <int O, int HS>
__global__ __launch_bounds__(256) void edge_kernel(const int* __restrict__ e, int E) {
    int gw = (blockIdx.x * 256 + threadIdx.x) >> 5;
    if (gw >= E) return;
    int lane = threadIdx.x & 31;
    int src = e[gw];
    int dst = e[E + gw];

    constexpr int V = O / 32;              // 4 or 2 halfs per lane per array
    constexpr int STRIDE = 6 * O;
    const __half* D = g_T + (size_t)dst * STRIDE;
    const __half* S = g_T + (size_t)src * STRIDE + 3 * O;
    int base = lane * V;

    float dq[V], sq[V], dk[V], sk[V], dv[V], sv[V];
    if constexpr (V == 4) {
        auto ld4 = [](const __half* p, float* o) {
            uint2 raw = *(const uint2*)p;
            __half2* h = (__half2*)&raw;
            float2 a = __half22float2(h[0]), b = __half22float2(h[1]);
            o[0] = a.x; o[1] = a.y; o[2] = b.x; o[3] = b.y;
        };
        ld4(D + base, dq);         ld4(D + O + base, dk);   ld4(D + 2 * O + base, dv);
        ld4(S + base, sq);         ld4(S + O + base, sk);   ld4(S + 2 * O + base, sv);
    } else {
        auto ld2 = [](const __half* p, float* o) {
            float2 a = __half22float2(*(const __half2*)p);
            o[0] = a.x; o[1] = a.y;
        };
        ld2(D + base, dq);         ld2(D + O + base, dk);   ld2(D + 2 * O + base, dv);
        ld2(S + base, sq);         ld2(S + O + base, sk);   ld2(S + 2 * O + base, sv);
    }

    // ew = sign(log|dst-src| - log 8): -1 if d<8 (incl d=0), 0 if d==8, +1 if d>8
    int dd = dst - src;
    if (dd < 0) dd = -dd;
    float ew = (dd > 8) ? 1.0f : ((dd == 8) ? 0.0f : -1.0f);

    const float scale = (HS == 16) ? 0.25f : 0.35355339059327373f;  // 1/sqrt(HS)
    float t[V];
    float m = -1e30f;
#pragma unroll
    for (int u = 0; u < V; u++) {
        t[u] = (dq[u] + sq[u]) * (dk[u] + sk[u]) * scale;
        m = fmaxf(m, t[u]);
    }
    m = fmaxf(m, __shfl_xor_sync(0xffffffffu, m, 1));
    m = fmaxf(m, __shfl_xor_sync(0xffffffffu, m, 2));
    float p[V];
    float ssum = 0.f;
#pragma unroll
    for (int u = 0; u < V; u++) {
        p[u] = __expf(t[u] - m);
        ssum += p[u];
    }
    ssum += __shfl_xor_sync(0xffffffffu, ssum, 1);
    ssum += __shfl_xor_sync(0xffffffffu, ssum, 2);
    float inv = 1.0f / ssum;

    float ctx[V];
#pragma unroll
    for (int u = 0; u < V; u++)
        ctx[u] = p[u] * inv * (dv[u] + sv[u]) * ew;

    float* outp = g_ACC + (size_t)dst * O + base;
    if constexpr (V == 4) {
        asm volatile("red.global.add.v4.f32 [%0], {%1, %2, %3, %4};"
                     :: "l"(outp), "f"(ctx[0]), "f"(ctx[1]), "f"(ctx[2]), "f"(ctx[3])
                     : "memory");
    } else {
        asm volatile("red.global.add.v2.f32 [%0], {%1, %2};"
                     :: "l"(outp), "f"(ctx[0]), "f"(ctx[1])
                     : "memory");
    }
    if (lane == 0) atomicAdd(&g_CNT[dst], 1);
}

// ---------------------------------------------------------------------------
__global__ void finalize_relu_kernel(float* __restrict__ out, int N, int O) {
    int i = blockIdx.x * blockDim.x + threadIdx.x;
    if (i >= N * O) return;
    int n = i / O;
    int c = g_CNT[n];
    float cf = (float)(c > 0 ? c : 1);
    out[i] = fmaxf(g_ACC[i] / cf, 0.f);
}

__global__ void finalize_res_kernel(float* __restrict__ out, int N, int O) {
    int i = blockIdx.x * blockDim.x + threadIdx.x;
    if (i >= N * O) return;
    int n = i / O;
    int c = g_CNT[n];
    float cf = (float)(c > 0 ? c : 1);
    out[i] = fmaxf(g_ACC[i] / cf + g_X0[i], 0.f);
}

// ---------------------------------------------------------------------------
extern "C" void kernel_launch(void* const* d_in, const int* in_sizes, int n_in,
                              void* d_out, int out_size) {
    const float* x   = (const float*)d_in[0];
    const int*   e0  = (const int*)d_in[1];
    const int*   e1  = (const int*)d_in[2];
    const int*   e2  = (const int*)d_in[3];
    // d_in[4] = batch (unused)
    const float* wq0 = (const float*)d_in[5],  *bq0 = (const float*)d_in[6];
    const float* wk0 = (const float*)d_in[7],  *bk0 = (const float*)d_in[8];
    const float* wv0 = (const float*)d_in[9],  *bv0 = (const float*)d_in[10];
    const float* wq1 = (const float*)d_in[11], *bq1 = (const float*)d_in[12];
    const float* wk1 = (const float*)d_in[13], *bk1 = (const float*)d_in[14];
    const float* wv1 = (const float*)d_in[15], *bv1 = (const float*)d_in[16];
    const float* wq2 = (const float*)d_in[17], *bq2 = (const float*)d_in[18];
    const float* wk2 = (const float*)d_in[19], *bk2 = (const float*)d_in[20];
    const float* wv2 = (const float*)d_in[21], *bv2 = (const float*)d_in[22];
    float* out = (float*)d_out;

    int N  = in_sizes[0] / 128;   // 50000
    int E0 = in_sizes[1] / 2;
    int E1 = in_sizes[2] / 2;
    int E2 = in_sizes[3] / 2;

    float *pX0 = nullptr, *pH = nullptr;
    cudaGetSymbolAddress((void**)&pX0, g_X0);
    cudaGetSymbolAddress((void**)&pH, g_H);

    // ---- Layer 0: C=128, O=128 ----
    {
        const int C = 128, O = 128, M = 6 * O;
        build_w_kernel<<<(C * M + 255) / 256, 256>>>(wq0, wk0, wv0, bq0, bk0, bv0, C, O);
        dim3 grid(M / 64, (N + 127) / 128);
        gemm_hmma_kernel<<<grid, 256>>>(x, N, C, M);
        zero_kernel<<<(N * O + 255) / 256, 256>>>(N * O);
        edge_kernel<128, 16><<<(E0 + 7) / 8, 256>>>(e0, E0);
        finalize_relu_kernel<<<(N * O + 255) / 256, 256>>>(pX0, N, O);
    }
    // ---- Layer 1: C=128, O=64 ----
    {
        const int C = 128, O = 64, M = 6 * O;
        build_w_kernel<<<(C * M + 255) / 256, 256>>>(wq1, wk1, wv1, bq1, bk1, bv1, C, O);
        dim3 grid(M / 64, (N + 127) / 128);
        gemm_hmma_kernel<<<grid, 256>>>(pX0, N, C, M);
        zero_kernel<<<(N * O + 255) / 256, 256>>>(N * O);
        edge_kernel<64, 8><<<(E1 + 7) / 8, 256>>>(e1, E1);
        finalize_relu_kernel<<<(N * O + 255) / 256, 256>>>(pH, N, O);
    }
    // ---- Layer 2: C=64, O=128 ----
    {
        const int C = 64, O = 128, M = 6 * O;
        build_w_kernel<<<(C * M + 255) / 256, 256>>>(wq2, wk2, wv2, bq2, bk2, bv2, C, O);
        dim3 grid(M / 64, (N + 127) / 128);
        gemm_hmma_kernel<<<grid, 256>>>(pH, N, C, M);
        zero_kernel<<<(N * O + 255) / 256, 256>>>(N * O);
        edge_kernel<128, 16><<<(E2 + 7) / 8, 256>>>(e2, E2);
        finalize_res_kernel<<<(N * O + 255) / 256, 256>>>(out, N, O);
    }
}

// round 4
// speedup vs baseline: 2.1230x; 1.1328x over previous
#include <cuda_runtime.h>
#include <cuda_fp16.h>
#include <cstdint>
#include <cstddef>

// ---------------------------------------------------------------------------
// EdgeConvEncoder: 3-layer EdgeConv GNN.
//   T = XH @ Wcomb  (fp16 cp.async double-buffered tensor-core GEMM)
//   per-edge softmax(q*k)*v*ew -> red.global into fp32 ACC
//   finalize: relu(ACC/max(cnt,1)) (+residual L2), zero ACC in place
// ---------------------------------------------------------------------------

#define NN 50000

__device__ __half g_T[NN * 768];     // node tables (fp16), max 6*O = 768 cols
__device__ float  g_ACC[NN * 128];   // segment-sum accumulator
__device__ int    g_CNT[NN];         // per-node edge counts
__device__ float  g_X0[NN * 128];    // layer-0 output fp32 (residual)
__device__ __half g_XH[NN * 128];    // current layer GEMM input (fp16)
__device__ __half g_W[128 * 768];    // combined weights (C x 6O), fp16
__device__ float  g_B[768];          // combined bias row (first 3O = bq|bk|bv)

// ---------------------------------------------------------------------------
__global__ void zero_kernel(int nAcc) {
    int i = blockIdx.x * blockDim.x + threadIdx.x;
    if (i < nAcc) g_ACC[i] = 0.f;
    if (i < NN) g_CNT[i] = 0;
}

__global__ void convert_x_kernel(const float* __restrict__ x, int n) {
    int i = blockIdx.x * blockDim.x + threadIdx.x;
    if (i < n) g_XH[i] = __float2half(x[i]);
}

// ---------------------------------------------------------------------------
// Build combined fp16 weight matrix + zero CNT (runs after previous finalize):
// cols [0,O)=wq_top-wq_bot [O,2O)=wk diff [2O,3O)=wv diff
// cols [3O,4O)=wq_bot      [4O,5O)=wk_bot [5O,6O)=wv_bot
// ---------------------------------------------------------------------------
__global__ void build_w_kernel(const float* __restrict__ wq, const float* __restrict__ wk,
                               const float* __restrict__ wv, const float* __restrict__ bq,
                               const float* __restrict__ bk, const float* __restrict__ bv,
                               int C, int O) {
    int M = 6 * O;
    int idx = blockIdx.x * blockDim.x + threadIdx.x;
    if (idx < C * M) {
        int c = idx / M;
        int m = idx - c * M;
        int which = m / O;
        int o = m - which * O;
        int qkv = which % 3;
        const float* w = (qkv == 0) ? wq : ((qkv == 1) ? wk : wv);
        float top = w[c * O + o];
        float bot = w[(C + c) * O + o];
        g_W[idx] = __float2half((which < 3) ? (top - bot) : bot);
    }
    if (idx < M) {
        int which = idx / O;
        int o = idx - which * O;
        float b = 0.f;
        if (which == 0) b = bq[o];
        else if (which == 1) b = bk[o];
        else if (which == 2) b = bv[o];
        g_B[idx] = b;
    }
    if (idx < NN) g_CNT[idx] = 0;
}

// ---------------------------------------------------------------------------
// fp16 TC GEMM: g_T[N x M] = g_XH[N x K] @ g_W[K x M] + g_B
// BM=128 BN=128 BK=32, 256 thr (8 warps 2x4), cp.async 2-stage, mma.m16n8k16.
// ---------------------------------------------------------------------------
__device__ __forceinline__ uint32_t smem_u32(const void* p) {
    return (uint32_t)__cvta_generic_to_shared(p);
}
#define CP_ASYNC16(dst, src) \
    asm volatile("cp.async.cg.shared.global [%0], [%1], 16;" :: "r"(dst), "l"(src))
#define CP_COMMIT() asm volatile("cp.async.commit_group;" ::: "memory")
#define CP_WAIT(n)  asm volatile("cp.async.wait_group %0;" :: "n"(n) : "memory")

__global__ __launch_bounds__(256) void gemm_hmma_kernel(const __half* __restrict__ A,
                                                        int N, int K, int M) {
    constexpr int AS = 40;   // A smem row stride (halfs): 32 + 8 pad
    constexpr int BS = 136;  // B smem row stride (halfs): 128 + 8 pad
    __shared__ __align__(16) __half Asm[2][128 * AS];  // 10240B/stage
    __shared__ __align__(16) __half Bsm[2][32 * BS];   // 8704B/stage

    int tid  = threadIdx.x;
    int lane = tid & 31;
    int wid  = tid >> 5;
    int warp_m = wid >> 2;   // 0..1 -> 64 rows
    int warp_n = wid & 3;    // 0..3 -> 32 cols
    int row0 = blockIdx.y * 128;
    int col0 = blockIdx.x * 128;

    float acc[4][4][4];
#pragma unroll
    for (int mt = 0; mt < 4; mt++)
#pragma unroll
        for (int nt = 0; nt < 4; nt++)
#pragma unroll
            for (int i = 0; i < 4; i++) acc[mt][nt][i] = 0.f;

    int nTiles = K >> 5;  // K/32

    auto load_tile = [&](int stage, int t) {
        int k0 = t << 5;
        // A: 128 rows x 32 halfs = 512 x 16B chunks
#pragma unroll
        for (int u = 0; u < 2; u++) {
            int idx = tid + u * 256;
            int r   = idx >> 2;
            int c   = (idx & 3) << 3;
            if (row0 + r < N) {
                CP_ASYNC16(smem_u32(&Asm[stage][r * AS + c]),
                           A + (size_t)(row0 + r) * K + k0 + c);
            }
        }
        // B: 32 rows x 128 halfs = 512 x 16B chunks
#pragma unroll
        for (int u = 0; u < 2; u++) {
            int idx = tid + u * 256;
            int r   = idx >> 4;
            int c   = (idx & 15) << 3;
            CP_ASYNC16(smem_u32(&Bsm[stage][r * BS + c]),
                       g_W + (size_t)(k0 + r) * M + col0 + c);
        }
        CP_COMMIT();
    };

    load_tile(0, 0);

    for (int t = 0; t < nTiles; t++) {
        int cur = t & 1;
        if (t + 1 < nTiles) {
            load_tile(cur ^ 1, t + 1);
            CP_WAIT(1);
        } else {
            CP_WAIT(0);
        }
        __syncthreads();

        int m0 = warp_m * 64;
        int n0 = warp_n * 32;
#pragma unroll
        for (int kk = 0; kk < 32; kk += 16) {
            uint32_t a[4][4];
#pragma unroll
            for (int mt = 0; mt < 4; mt++) {
                uint32_t addr = smem_u32(&Asm[cur][(m0 + mt * 16 + (lane & 15)) * AS +
                                                  kk + (lane >> 4) * 8]);
                asm volatile("ldmatrix.sync.aligned.m8n8.x4.shared.b16 {%0,%1,%2,%3}, [%4];"
                             : "=r"(a[mt][0]), "=r"(a[mt][1]), "=r"(a[mt][2]), "=r"(a[mt][3])
                             : "r"(addr));
            }
            uint32_t b[4][2];
#pragma unroll
            for (int np = 0; np < 2; np++) {
                uint32_t addr = smem_u32(&Bsm[cur][(kk + (lane & 15)) * BS +
                                                   n0 + np * 16 + (lane >> 4) * 8]);
                uint32_t r0, r1, r2, r3;
                asm volatile("ldmatrix.sync.aligned.m8n8.x4.trans.shared.b16 {%0,%1,%2,%3}, [%4];"
                             : "=r"(r0), "=r"(r1), "=r"(r2), "=r"(r3)
                             : "r"(addr));
                b[np * 2 + 0][0] = r0; b[np * 2 + 0][1] = r1;
                b[np * 2 + 1][0] = r2; b[np * 2 + 1][1] = r3;
            }
#pragma unroll
            for (int mt = 0; mt < 4; mt++)
#pragma unroll
                for (int nt = 0; nt < 4; nt++) {
                    asm volatile(
                        "mma.sync.aligned.m16n8k16.row.col.f32.f16.f16.f32 "
                        "{%0,%1,%2,%3}, {%4,%5,%6,%7}, {%8,%9}, {%0,%1,%2,%3};"
                        : "+f"(acc[mt][nt][0]), "+f"(acc[mt][nt][1]),
                          "+f"(acc[mt][nt][2]), "+f"(acc[mt][nt][3])
                        : "r"(a[mt][0]), "r"(a[mt][1]), "r"(a[mt][2]), "r"(a[mt][3]),
                          "r"(b[nt][0]), "r"(b[nt][1]));
                }
        }
        __syncthreads();
    }

    // epilogue: + bias, fp16 store
    int g  = lane >> 2;
    int t4 = lane & 3;
#pragma unroll
    for (int mt = 0; mt < 4; mt++) {
#pragma unroll
        for (int nt = 0; nt < 4; nt++) {
            int col = col0 + warp_n * 32 + nt * 8 + t4 * 2;
            float bx = g_B[col], by = g_B[col + 1];
#pragma unroll
            for (int h = 0; h < 2; h++) {
                int r = row0 + warp_m * 64 + mt * 16 + g + h * 8;
                if (r < N) {
                    __half2 o = __floats2half2_rn(acc[mt][nt][h * 2 + 0] + bx,
                                                  acc[mt][nt][h * 2 + 1] + by);
                    *(__half2*)(g_T + (size_t)r * M + col) = o;
                }
            }
        }
    }
}

// ---------------------------------------------------------------------------
// Edge kernel: one warp per edge. T row (fp16) per node:
//   [0,O)q_dst [O,2O)k_dst [2O,3O)v_dst [3O,4O)q_src [4O,5O)k_src [5O,6O)v_src
// softmax over HS channels without max-subtract (scores are O(1), safe).
// ---------------------------------------------------------------------------
template <int O, int HS>
__global__ __launch_bounds__(256) void edge_kernel(const int* __restrict__ e, int E) {
    int gw = (blockIdx.x * 256 + threadIdx.x) >> 5;
    if (gw >= E) return;
    int lane = threadIdx.x & 31;
    int src = e[gw];
    int dst = e[E + gw];

    constexpr int V = O / 32;
    constexpr int STRIDE = 6 * O;
    const __half* D = g_T + (size_t)dst * STRIDE;
    const __half* S = g_T + (size_t)src * STRIDE + 3 * O;
    int base = lane * V;

    float dq[V], sq[V], dk[V], sk[V], dv[V], sv[V];
    if constexpr (V == 4) {
        auto ld4 = [](const __half* p, float* o) {
            uint2 raw = *(const uint2*)p;
            __half2* h = (__half2*)&raw;
            float2 a = __half22float2(h[0]), b = __half22float2(h[1]);
            o[0] = a.x; o[1] = a.y; o[2] = b.x; o[3] = b.y;
        };
        ld4(D + base, dq);  ld4(D + O + base, dk);  ld4(D + 2 * O + base, dv);
        ld4(S + base, sq);  ld4(S + O + base, sk);  ld4(S + 2 * O + base, sv);
    } else {
        auto ld2 = [](const __half* p, float* o) {
            float2 a = __half22float2(*(const __half2*)p);
            o[0] = a.x; o[1] = a.y;
        };
        ld2(D + base, dq);  ld2(D + O + base, dk);  ld2(D + 2 * O + base, dv);
        ld2(S + base, sq);  ld2(S + O + base, sk);  ld2(S + 2 * O + base, sv);
    }

    int dd = dst - src;
    if (dd < 0) dd = -dd;
    float ew = (dd > 8) ? 1.0f : ((dd == 8) ? 0.0f : -1.0f);

    const float scale = (HS == 16) ? 0.25f : 0.35355339059327373f;  // 1/sqrt(HS)
    float p[V];
    float ssum = 0.f;
#pragma unroll
    for (int u = 0; u < V; u++) {
        float t = (dq[u] + sq[u]) * (dk[u] + sk[u]) * scale;
        p[u] = __expf(t);
        ssum += p[u];
    }
    ssum += __shfl_xor_sync(0xffffffffu, ssum, 1);
    ssum += __shfl_xor_sync(0xffffffffu, ssum, 2);
    float inv = __fdividef(1.0f, ssum);

    float ctx[V];
#pragma unroll
    for (int u = 0; u < V; u++)
        ctx[u] = p[u] * inv * (dv[u] + sv[u]) * ew;

    float* outp = g_ACC + (size_t)dst * O + base;
    if constexpr (V == 4) {
        asm volatile("red.global.add.v4.f32 [%0], {%1, %2, %3, %4};"
                     :: "l"(outp), "f"(ctx[0]), "f"(ctx[1]), "f"(ctx[2]), "f"(ctx[3])
                     : "memory");
    } else {
        asm volatile("red.global.add.v2.f32 [%0], {%1, %2};"
                     :: "l"(outp), "f"(ctx[0]), "f"(ctx[1])
                     : "memory");
    }
    if (lane == 0) atomicAdd(&g_CNT[dst], 1);
}

// ---------------------------------------------------------------------------
// Finalize variants. Each reads ACC then zeroes it in place (same thread).
// ---------------------------------------------------------------------------
__global__ void finalize0_kernel(int N) {   // layer0: X0 fp32 + XH fp16, O=128
    int i = blockIdx.x * blockDim.x + threadIdx.x;
    if (i >= N * 128) return;
    int n = i >> 7;
    int c = g_CNT[n];
    float cf = (float)(c > 0 ? c : 1);
    float v = fmaxf(g_ACC[i] / cf, 0.f);
    g_ACC[i] = 0.f;
    g_X0[i] = v;
    g_XH[i] = __float2half(v);
}

__global__ void finalize1_kernel(int N) {   // layer1: XH fp16 only, O=64
    int i = blockIdx.x * blockDim.x + threadIdx.x;
    if (i >= N * 64) return;
    int n = i >> 6;
    int c = g_CNT[n];
    float cf = (float)(c > 0 ? c : 1);
    float v = fmaxf(g_ACC[i] / cf, 0.f);
    g_ACC[i] = 0.f;
    g_XH[i] = __float2half(v);
}

__global__ void finalize2_kernel(float* __restrict__ out, int N) {  // + residual
    int i = blockIdx.x * blockDim.x + threadIdx.x;
    if (i >= N * 128) return;
    int n = i >> 7;
    int c = g_CNT[n];
    float cf = (float)(c > 0 ? c : 1);
    out[i] = fmaxf(g_ACC[i] / cf + g_X0[i], 0.f);
}

// ---------------------------------------------------------------------------
extern "C" void kernel_launch(void* const* d_in, const int* in_sizes, int n_in,
                              void* d_out, int out_size) {
    const float* x   = (const float*)d_in[0];
    const int*   e0  = (const int*)d_in[1];
    const int*   e1  = (const int*)d_in[2];
    const int*   e2  = (const int*)d_in[3];
    // d_in[4] = batch (unused)
    const float* wq0 = (const float*)d_in[5],  *bq0 = (const float*)d_in[6];
    const float* wk0 = (const float*)d_in[7],  *bk0 = (const float*)d_in[8];
    const float* wv0 = (const float*)d_in[9],  *bv0 = (const float*)d_in[10];
    const float* wq1 = (const float*)d_in[11], *bq1 = (const float*)d_in[12];
    const float* wk1 = (const float*)d_in[13], *bk1 = (const float*)d_in[14];
    const float* wv1 = (const float*)d_in[15], *bv1 = (const float*)d_in[16];
    const float* wq2 = (const float*)d_in[17], *bq2 = (const float*)d_in[18];
    const float* wk2 = (const float*)d_in[19], *bk2 = (const float*)d_in[20];
    const float* wv2 = (const float*)d_in[21], *bv2 = (const float*)d_in[22];
    float* out = (float*)d_out;

    int N  = in_sizes[0] / 128;   // 50000
    int E0 = in_sizes[1] / 2;
    int E1 = in_sizes[2] / 2;
    int E2 = in_sizes[3] / 2;

    __half* pXH = nullptr;
    cudaGetSymbolAddress((void**)&pXH, g_XH);

    // initial: zero ACC+CNT, convert x to fp16
    zero_kernel<<<(N * 128 + 255) / 256, 256>>>(N * 128);
    convert_x_kernel<<<(N * 128 + 255) / 256, 256>>>(x, N * 128);

    // ---- Layer 0: C=128, O=128, M=768 ----
    {
        const int C = 128, O = 128, M = 6 * O;
        int bw = (C * M > NN ? C * M : NN);
        build_w_kernel<<<(bw + 255) / 256, 256>>>(wq0, wk0, wv0, bq0, bk0, bv0, C, O);
        dim3 grid(M / 128, (N + 127) / 128);
        gemm_hmma_kernel<<<grid, 256>>>(pXH, N, C, M);
        edge_kernel<128, 16><<<(E0 + 7) / 8, 256>>>(e0, E0);
        finalize0_kernel<<<(N * 128 + 255) / 256, 256>>>(N);
    }
    // ---- Layer 1: C=128, O=64, M=384 ----
    {
        const int C = 128, O = 64, M = 6 * O;
        int bw = (C * M > NN ? C * M : NN);
        build_w_kernel<<<(bw + 255) / 256, 256>>>(wq1, wk1, wv1, bq1, bk1, bv1, C, O);
        dim3 grid(M / 128, (N + 127) / 128);
        gemm_hmma_kernel<<<grid, 256>>>(pXH, N, C, M);
        edge_kernel<64, 8><<<(E1 + 7) / 8, 256>>>(e1, E1);
        finalize1_kernel<<<(N * 64 + 255) / 256, 256>>>(N);
    }
    // ---- Layer 2: C=64, O=128, M=768 ----
    {
        const int C = 64, O = 128, M = 6 * O;
        int bw = (C * M > NN ? C * M : NN);
        build_w_kernel<<<(bw + 255) / 256, 256>>>(wq2, wk2, wv2, bq2, bk2, bv2, C, O);
        dim3 grid(M / 128, (N + 127) / 128);
        gemm_hmma_kernel<<<grid, 256>>>(pXH, N, C, M);
        edge_kernel<128, 16><<<(E2 + 7) / 8, 256>>>(e2, E2);
        finalize2_kernel<<<(N * 128 + 255) / 256, 256>>>(out, N);
    }
}

// round 5
// speedup vs baseline: 2.5739x; 1.2124x over previous
#include <cuda_runtime.h>
#include <cuda_fp16.h>
#include <cstdint>
#include <cstddef>

// ---------------------------------------------------------------------------
// EdgeConvEncoder: 3-layer EdgeConv GNN.
//   T = XH @ Wcomb       (fp16 cp.async double-buffered tensor-core GEMM)
//   counting-sort edges by dst, then per-node warp aggregation (no atomics),
//   finalize fused into the aggregate kernel.
// ---------------------------------------------------------------------------

#define NN 50000
#define MAXE 500000

__device__ __half g_T[NN * 768];     // node tables (fp16), max 6*O = 768 cols
__device__ int    g_CNT[NN];         // per-node edge counts (histogram)
__device__ int    g_OFF[NN];         // exclusive scan of CNT
__device__ int    g_POS[NN];         // scatter cursors
__device__ int    g_PART[256];       // scan partials
__device__ int    g_SRCS[MAXE];      // src ids sorted by dst
__device__ float  g_X0[NN * 128];    // layer-0 output fp32 (residual)
__device__ __half g_XH[NN * 128];    // current layer GEMM input (fp16)
__device__ __half g_W[128 * 768];    // combined weights (C x 6O), fp16
__device__ float  g_B[768];          // combined bias row

// ---------------------------------------------------------------------------
__global__ void convert_x_kernel(const float* __restrict__ x, int n) {
    int i = blockIdx.x * blockDim.x + threadIdx.x;
    if (i < n) g_XH[i] = __float2half(x[i]);
}

// ---------------------------------------------------------------------------
// Build combined fp16 weight matrix + zero CNT for this layer's histogram.
// cols [0,O)=wq_top-wq_bot [O,2O)=wk diff [2O,3O)=wv diff
// cols [3O,4O)=wq_bot      [4O,5O)=wk_bot [5O,6O)=wv_bot
// ---------------------------------------------------------------------------
__global__ void build_w_kernel(const float* __restrict__ wq, const float* __restrict__ wk,
                               const float* __restrict__ wv, const float* __restrict__ bq,
                               const float* __restrict__ bk, const float* __restrict__ bv,
                               int C, int O) {
    int M = 6 * O;
    int idx = blockIdx.x * blockDim.x + threadIdx.x;
    if (idx < C * M) {
        int c = idx / M;
        int m = idx - c * M;
        int which = m / O;
        int o = m - which * O;
        int qkv = which % 3;
        const float* w = (qkv == 0) ? wq : ((qkv == 1) ? wk : wv);
        float top = w[c * O + o];
        float bot = w[(C + c) * O + o];
        g_W[idx] = __float2half((which < 3) ? (top - bot) : bot);
    }
    if (idx < M) {
        int which = idx / O;
        int o = idx - which * O;
        float b = 0.f;
        if (which == 0) b = bq[o];
        else if (which == 1) b = bk[o];
        else if (which == 2) b = bv[o];
        g_B[idx] = b;
    }
    if (idx < NN) g_CNT[idx] = 0;
}

// ---------------------------------------------------------------------------
// Counting sort of edges by dst.
// ---------------------------------------------------------------------------
__global__ void hist_kernel(const int* __restrict__ e, int E) {
    int i = blockIdx.x * blockDim.x + threadIdx.x;
    if (i < E) atomicAdd(&g_CNT[e[E + i]], 1);
}

__global__ void scan1_kernel(int nblk_total) {
    __shared__ int s[256];
    int t = threadIdx.x;
    int i = blockIdx.x * 256 + t;
    int v = (i < NN) ? g_CNT[i] : 0;
    s[t] = v;
    __syncthreads();
#pragma unroll
    for (int d = 1; d < 256; d <<= 1) {
        int x = (t >= d) ? s[t - d] : 0;
        __syncthreads();
        s[t] += x;
        __syncthreads();
    }
    if (i < NN) g_OFF[i] = s[t] - v;            // exclusive
    if (t == 255) g_PART[blockIdx.x] = s[255];  // block total
}

__global__ void scan2_kernel(int P) {
    __shared__ int s[256];
    int t = threadIdx.x;
    int v = (t < P) ? g_PART[t] : 0;
    s[t] = v;
    __syncthreads();
#pragma unroll
    for (int d = 1; d < 256; d <<= 1) {
        int x = (t >= d) ? s[t - d] : 0;
        __syncthreads();
        s[t] += x;
        __syncthreads();
    }
    if (t < P) g_PART[t] = s[t] - v;            // exclusive over partials
}

__global__ void scan3_kernel() {
    int i = blockIdx.x * 256 + threadIdx.x;
    if (i < NN) {
        int o = g_OFF[i] + g_PART[blockIdx.x];
        g_OFF[i] = o;
        g_POS[i] = o;
    }
}

__global__ void scatter_kernel(const int* __restrict__ e, int E) {
    int i = blockIdx.x * blockDim.x + threadIdx.x;
    if (i < E) {
        int src = e[i];
        int dst = e[E + i];
        int pos = atomicAdd(&g_POS[dst], 1);
        g_SRCS[pos] = src;
    }
}

// ---------------------------------------------------------------------------
// fp16 TC GEMM: g_T[N x M] = g_XH[N x K] @ g_W[K x M] + g_B
// BM=128 BN=128 BK=32, 256 thr (8 warps 2x4), cp.async 2-stage, mma.m16n8k16.
// ---------------------------------------------------------------------------
__device__ __forceinline__ uint32_t smem_u32(const void* p) {
    return (uint32_t)__cvta_generic_to_shared(p);
}
#define CP_ASYNC16(dst, src) \
    asm volatile("cp.async.cg.shared.global [%0], [%1], 16;" :: "r"(dst), "l"(src))
#define CP_COMMIT() asm volatile("cp.async.commit_group;" ::: "memory")
#define CP_WAIT(n)  asm volatile("cp.async.wait_group %0;" :: "n"(n) : "memory")

__global__ __launch_bounds__(256) void gemm_hmma_kernel(const __half* __restrict__ A,
                                                        int N, int K, int M) {
    constexpr int AS = 40;
    constexpr int BS = 136;
    __shared__ __align__(16) __half Asm[2][128 * AS];
    __shared__ __align__(16) __half Bsm[2][32 * BS];

    int tid  = threadIdx.x;
    int lane = tid & 31;
    int wid  = tid >> 5;
    int warp_m = wid >> 2;
    int warp_n = wid & 3;
    int row0 = blockIdx.y * 128;
    int col0 = blockIdx.x * 128;

    float acc[4][4][4];
#pragma unroll
    for (int mt = 0; mt < 4; mt++)
#pragma unroll
        for (int nt = 0; nt < 4; nt++)
#pragma unroll
            for (int i = 0; i < 4; i++) acc[mt][nt][i] = 0.f;

    int nTiles = K >> 5;

    auto load_tile = [&](int stage, int t) {
        int k0 = t << 5;
#pragma unroll
        for (int u = 0; u < 2; u++) {
            int idx = tid + u * 256;
            int r   = idx >> 2;
            int c   = (idx & 3) << 3;
            if (row0 + r < N) {
                CP_ASYNC16(smem_u32(&Asm[stage][r * AS + c]),
                           A + (size_t)(row0 + r) * K + k0 + c);
            }
        }
#pragma unroll
        for (int u = 0; u < 2; u++) {
            int idx = tid + u * 256;
            int r   = idx >> 4;
            int c   = (idx & 15) << 3;
            CP_ASYNC16(smem_u32(&Bsm[stage][r * BS + c]),
                       g_W + (size_t)(k0 + r) * M + col0 + c);
        }
        CP_COMMIT();
    };

    load_tile(0, 0);

    for (int t = 0; t < nTiles; t++) {
        int cur = t & 1;
        if (t + 1 < nTiles) {
            load_tile(cur ^ 1, t + 1);
            CP_WAIT(1);
        } else {
            CP_WAIT(0);
        }
        __syncthreads();

        int m0 = warp_m * 64;
        int n0 = warp_n * 32;
#pragma unroll
        for (int kk = 0; kk < 32; kk += 16) {
            uint32_t a[4][4];
#pragma unroll
            for (int mt = 0; mt < 4; mt++) {
                uint32_t addr = smem_u32(&Asm[cur][(m0 + mt * 16 + (lane & 15)) * AS +
                                                  kk + (lane >> 4) * 8]);
                asm volatile("ldmatrix.sync.aligned.m8n8.x4.shared.b16 {%0,%1,%2,%3}, [%4];"
                             : "=r"(a[mt][0]), "=r"(a[mt][1]), "=r"(a[mt][2]), "=r"(a[mt][3])
                             : "r"(addr));
            }
            uint32_t b[4][2];
#pragma unroll
            for (int np = 0; np < 2; np++) {
                uint32_t addr = smem_u32(&Bsm[cur][(kk + (lane & 15)) * BS +
                                                   n0 + np * 16 + (lane >> 4) * 8]);
                uint32_t r0, r1, r2, r3;
                asm volatile("ldmatrix.sync.aligned.m8n8.x4.trans.shared.b16 {%0,%1,%2,%3}, [%4];"
                             : "=r"(r0), "=r"(r1), "=r"(r2), "=r"(r3)
                             : "r"(addr));
                b[np * 2 + 0][0] = r0; b[np * 2 + 0][1] = r1;
                b[np * 2 + 1][0] = r2; b[np * 2 + 1][1] = r3;
            }
#pragma unroll
            for (int mt = 0; mt < 4; mt++)
#pragma unroll
                for (int nt = 0; nt < 4; nt++) {
                    asm volatile(
                        "mma.sync.aligned.m16n8k16.row.col.f32.f16.f16.f32 "
                        "{%0,%1,%2,%3}, {%4,%5,%6,%7}, {%8,%9}, {%0,%1,%2,%3};"
                        : "+f"(acc[mt][nt][0]), "+f"(acc[mt][nt][1]),
                          "+f"(acc[mt][nt][2]), "+f"(acc[mt][nt][3])
                        : "r"(a[mt][0]), "r"(a[mt][1]), "r"(a[mt][2]), "r"(a[mt][3]),
                          "r"(b[nt][0]), "r"(b[nt][1]));
                }
        }
        __syncthreads();
    }

    int g  = lane >> 2;
    int t4 = lane & 3;
#pragma unroll
    for (int mt = 0; mt < 4; mt++) {
#pragma unroll
        for (int nt = 0; nt < 4; nt++) {
            int col = col0 + warp_n * 32 + nt * 8 + t4 * 2;
            float bx = g_B[col], by = g_B[col + 1];
#pragma unroll
            for (int h = 0; h < 2; h++) {
                int r = row0 + warp_m * 64 + mt * 16 + g + h * 8;
                if (r < N) {
                    __half2 o = __floats2half2_rn(acc[mt][nt][h * 2 + 0] + bx,
                                                  acc[mt][nt][h * 2 + 1] + by);
                    *(__half2*)(g_T + (size_t)r * M + col) = o;
                }
            }
        }
    }
}

// ---------------------------------------------------------------------------
// Aggregate: one warp per dst node. Loads dst q/k/v halves once, loops over
// sorted edges loading only src halves. Fused finalize:
//   MODE 0: X0 = relu(mean), XH = half(X0)         (O=128)
//   MODE 1: XH = half(relu(mean))                  (O=64)
//   MODE 2: out = relu(mean + X0)                  (O=128)
// ---------------------------------------------------------------------------
template <int O, int HS, int MODE>
__global__ __launch_bounds__(256) void agg_kernel(float* __restrict__ out, int N) {
    int n = (blockIdx.x * 256 + threadIdx.x) >> 5;
    if (n >= N) return;
    int lane = threadIdx.x & 31;
    constexpr int V = O / 32;
    int base = lane * V;

    int cnt = g_CNT[n];
    float res[V];
#pragma unroll
    for (int u = 0; u < V; u++) res[u] = 0.f;

    if (cnt > 0) {
        constexpr int STRIDE = 6 * O;
        const __half* D = g_T + (size_t)n * STRIDE;
        float dq[V], dk[V], dv[V];
        auto ld4 = [](const __half* p, float* o) {
            uint2 raw = *(const uint2*)p;
            __half2* h = (__half2*)&raw;
            float2 a = __half22float2(h[0]), b = __half22float2(h[1]);
            o[0] = a.x; o[1] = a.y; o[2] = b.x; o[3] = b.y;
        };
        auto ld2 = [](const __half* p, float* o) {
            float2 a = __half22float2(*(const __half2*)p);
            o[0] = a.x; o[1] = a.y;
        };
        if constexpr (V == 4) {
            ld4(D + base, dq); ld4(D + O + base, dk); ld4(D + 2 * O + base, dv);
        } else {
            ld2(D + base, dq); ld2(D + O + base, dk); ld2(D + 2 * O + base, dv);
        }

        const float scale = (HS == 16) ? 0.25f : 0.35355339059327373f;
        int off = g_OFF[n];
        int src = g_SRCS[off];
        for (int j = 0; j < cnt; j++) {
            int nsrc = (j + 1 < cnt) ? g_SRCS[off + j + 1] : 0;
            const __half* S = g_T + (size_t)src * STRIDE + 3 * O;
            float sq[V], sk[V], sv[V];
            if constexpr (V == 4) {
                ld4(S + base, sq); ld4(S + O + base, sk); ld4(S + 2 * O + base, sv);
            } else {
                ld2(S + base, sq); ld2(S + O + base, sk); ld2(S + 2 * O + base, sv);
            }
            int dd = n - src;
            if (dd < 0) dd = -dd;
            float ew = (dd > 8) ? 1.0f : ((dd == 8) ? 0.0f : -1.0f);

            float p[V];
            float ssum = 0.f;
#pragma unroll
            for (int u = 0; u < V; u++) {
                float t = (dq[u] + sq[u]) * (dk[u] + sk[u]) * scale;
                p[u] = __expf(t);
                ssum += p[u];
            }
            ssum += __shfl_xor_sync(0xffffffffu, ssum, 1);
            ssum += __shfl_xor_sync(0xffffffffu, ssum, 2);
            float w = __fdividef(ew, ssum);
#pragma unroll
            for (int u = 0; u < V; u++)
                res[u] = fmaf(p[u] * (dv[u] + sv[u]), w, res[u]);
            src = nsrc;
        }
        float invc = __fdividef(1.0f, (float)cnt);
#pragma unroll
        for (int u = 0; u < V; u++) res[u] *= invc;
    }

    if constexpr (MODE == 0) {
        float v[4];
#pragma unroll
        for (int u = 0; u < 4; u++) v[u] = fmaxf(res[u], 0.f);
        *(float4*)(g_X0 + (size_t)n * 128 + base) = make_float4(v[0], v[1], v[2], v[3]);
        __half2 h[2];
        h[0] = __floats2half2_rn(v[0], v[1]);
        h[1] = __floats2half2_rn(v[2], v[3]);
        *(uint2*)(g_XH + (size_t)n * 128 + base) = *(uint2*)h;
    } else if constexpr (MODE == 1) {
        __half2 h = __floats2half2_rn(fmaxf(res[0], 0.f), fmaxf(res[1], 0.f));
        *(__half2*)(g_XH + (size_t)n * 64 + base) = h;
    } else {
        float4 x0 = *(const float4*)(g_X0 + (size_t)n * 128 + base);
        float4 o;
        o.x = fmaxf(res[0] + x0.x, 0.f);
        o.y = fmaxf(res[1] + x0.y, 0.f);
        o.z = fmaxf(res[2] + x0.z, 0.f);
        o.w = fmaxf(res[3] + x0.w, 0.f);
        *(float4*)(out + (size_t)n * 128 + base) = o;
    }
}

// ---------------------------------------------------------------------------
static inline void sort_edges(const int* e, int E) {
    int nblk = (NN + 255) / 256;  // 196
    hist_kernel<<<(E + 255) / 256, 256>>>(e, E);
    scan1_kernel<<<nblk, 256>>>(nblk);
    scan2_kernel<<<1, 256>>>(nblk);
    scan3_kernel<<<nblk, 256>>>();
    scatter_kernel<<<(E + 255) / 256, 256>>>(e, E);
}

extern "C" void kernel_launch(void* const* d_in, const int* in_sizes, int n_in,
                              void* d_out, int out_size) {
    const float* x   = (const float*)d_in[0];
    const int*   e0  = (const int*)d_in[1];
    const int*   e1  = (const int*)d_in[2];
    const int*   e2  = (const int*)d_in[3];
    // d_in[4] = batch (unused)
    const float* wq0 = (const float*)d_in[5],  *bq0 = (const float*)d_in[6];
    const float* wk0 = (const float*)d_in[7],  *bk0 = (const float*)d_in[8];
    const float* wv0 = (const float*)d_in[9],  *bv0 = (const float*)d_in[10];
    const float* wq1 = (const float*)d_in[11], *bq1 = (const float*)d_in[12];
    const float* wk1 = (const float*)d_in[13], *bk1 = (const float*)d_in[14];
    const float* wv1 = (const float*)d_in[15], *bv1 = (const float*)d_in[16];
    const float* wq2 = (const float*)d_in[17], *bq2 = (const float*)d_in[18];
    const float* wk2 = (const float*)d_in[19], *bk2 = (const float*)d_in[20];
    const float* wv2 = (const float*)d_in[21], *bv2 = (const float*)d_in[22];
    float* out = (float*)d_out;

    int N  = in_sizes[0] / 128;   // 50000
    int E0 = in_sizes[1] / 2;
    int E1 = in_sizes[2] / 2;
    int E2 = in_sizes[3] / 2;

    __half* pXH = nullptr;
    cudaGetSymbolAddress((void**)&pXH, g_XH);

    convert_x_kernel<<<(N * 128 + 255) / 256, 256>>>(x, N * 128);

    int aggGrid = (N * 32 + 255) / 256;

    // ---- Layer 0: C=128, O=128, M=768 ----
    {
        const int C = 128, O = 128, M = 6 * O;
        int bw = (C * M > NN ? C * M : NN);
        build_w_kernel<<<(bw + 255) / 256, 256>>>(wq0, wk0, wv0, bq0, bk0, bv0, C, O);
        dim3 grid(M / 128, (N + 127) / 128);
        gemm_hmma_kernel<<<grid, 256>>>(pXH, N, C, M);
        sort_edges(e0, E0);
        agg_kernel<128, 16, 0><<<aggGrid, 256>>>(nullptr, N);
    }
    // ---- Layer 1: C=128, O=64, M=384 ----
    {
        const int C = 128, O = 64, M = 6 * O;
        int bw = (C * M > NN ? C * M : NN);
        build_w_kernel<<<(bw + 255) / 256, 256>>>(wq1, wk1, wv1, bq1, bk1, bv1, C, O);
        dim3 grid(M / 128, (N + 127) / 128);
        gemm_hmma_kernel<<<grid, 256>>>(pXH, N, C, M);
        sort_edges(e1, E1);
        agg_kernel<64, 8, 1><<<aggGrid, 256>>>(nullptr, N);
    }
    // ---- Layer 2: C=64, O=128, M=768 ----
    {
        const int C = 64, O = 128, M = 6 * O;
        int bw = (C * M > NN ? C * M : NN);
        build_w_kernel<<<(bw + 255) / 256, 256>>>(wq2, wk2, wv2, bq2, bk2, bv2, C, O);
        dim3 grid(M / 128, (N + 127) / 128);
        gemm_hmma_kernel<<<grid, 256>>>(pXH, N, C, M);
        sort_edges(e2, E2);
        agg_kernel<128, 16, 2><<<aggGrid, 256>>>(out, N);
    }
}

// round 6
// speedup vs baseline: 2.6327x; 1.0228x over previous
#include <cuda_runtime.h>
#include <cuda_fp16.h>
#include <cstdint>
#include <cstddef>

// ---------------------------------------------------------------------------
// EdgeConvEncoder: 3-layer EdgeConv GNN.
//   up-front: batched counting sort of all 3 edge lists by dst
//   per layer: T = XH @ Wcomb (B-resident fp16 TC GEMM), warp-per-node
//              aggregation with software-pipelined src loads, fused finalize.
// ---------------------------------------------------------------------------

#define NN 50000
#define MAXE 500000

__device__ __half g_T[NN * 768];       // node tables (fp16), max 6*O cols
__device__ int    g_CNT3[3 * NN];      // per-layer histograms
__device__ int    g_OFF3[3 * NN];      // per-layer exclusive scans
__device__ int    g_POS3[3 * NN];      // scatter cursors
__device__ int    g_PART3[3 * 256];    // scan partials
__device__ int    g_SRCS3[3 * MAXE];   // src ids sorted by dst, per layer
__device__ float  g_X0[NN * 128];      // layer-0 output fp32 (residual)
__device__ __half g_XH[NN * 128];      // current GEMM input (fp16)
__device__ __half g_W[128 * 768];      // combined weights (C x 6O), fp16
__device__ float  g_B[768];            // combined bias row

// ---------------------------------------------------------------------------
__global__ void convert_x_kernel(const float* __restrict__ x, int n) {
    int i = blockIdx.x * blockDim.x + threadIdx.x;
    if (i < n) g_XH[i] = __float2half(x[i]);
}

__global__ void zero3_kernel() {
    int i = blockIdx.x * blockDim.x + threadIdx.x;
    if (i < 3 * NN) g_CNT3[i] = 0;
}

// ---------------------------------------------------------------------------
// Batched counting sort (blockIdx.y = layer).
// ---------------------------------------------------------------------------
__global__ void hist3_kernel(const int* __restrict__ e0, const int* __restrict__ e1,
                             const int* __restrict__ e2, int E) {
    int L = blockIdx.y;
    const int* e = (L == 0) ? e0 : ((L == 1) ? e1 : e2);
    int i = blockIdx.x * blockDim.x + threadIdx.x;
    if (i < E) atomicAdd(&g_CNT3[L * NN + e[E + i]], 1);
}

__global__ void scan1_kernel() {
    int L = blockIdx.y;
    __shared__ int s[256];
    int t = threadIdx.x;
    int i = blockIdx.x * 256 + t;
    int v = (i < NN) ? g_CNT3[L * NN + i] : 0;
    s[t] = v;
    __syncthreads();
#pragma unroll
    for (int d = 1; d < 256; d <<= 1) {
        int x = (t >= d) ? s[t - d] : 0;
        __syncthreads();
        s[t] += x;
        __syncthreads();
    }
    if (i < NN) g_OFF3[L * NN + i] = s[t] - v;
    if (t == 255) g_PART3[L * 256 + blockIdx.x] = s[255];
}

__global__ void scan2_kernel(int P) {
    int L = blockIdx.y;
    __shared__ int s[256];
    int t = threadIdx.x;
    int v = (t < P) ? g_PART3[L * 256 + t] : 0;
    s[t] = v;
    __syncthreads();
#pragma unroll
    for (int d = 1; d < 256; d <<= 1) {
        int x = (t >= d) ? s[t - d] : 0;
        __syncthreads();
        s[t] += x;
        __syncthreads();
    }
    if (t < P) g_PART3[L * 256 + t] = s[t] - v;
}

__global__ void scan3_kernel() {
    int L = blockIdx.y;
    int i = blockIdx.x * 256 + threadIdx.x;
    if (i < NN) {
        int o = g_OFF3[L * NN + i] + g_PART3[L * 256 + blockIdx.x];
        g_OFF3[L * NN + i] = o;
        g_POS3[L * NN + i] = o;
    }
}

__global__ void scatter3_kernel(const int* __restrict__ e0, const int* __restrict__ e1,
                                const int* __restrict__ e2, int E) {
    int L = blockIdx.y;
    const int* e = (L == 0) ? e0 : ((L == 1) ? e1 : e2);
    int i = blockIdx.x * blockDim.x + threadIdx.x;
    if (i < E) {
        int src = e[i];
        int dst = e[E + i];
        int pos = atomicAdd(&g_POS3[L * NN + dst], 1);
        g_SRCS3[L * MAXE + pos] = src;
    }
}

// ---------------------------------------------------------------------------
// Build combined fp16 weight matrix:
// cols [0,O)=wq_top-wq_bot [O,2O)=wk diff [2O,3O)=wv diff
// cols [3O,4O)=wq_bot      [4O,5O)=wk_bot [5O,6O)=wv_bot
// ---------------------------------------------------------------------------
__global__ void build_w_kernel(const float* __restrict__ wq, const float* __restrict__ wk,
                               const float* __restrict__ wv, const float* __restrict__ bq,
                               const float* __restrict__ bk, const float* __restrict__ bv,
                               int C, int O) {
    int M = 6 * O;
    int idx = blockIdx.x * blockDim.x + threadIdx.x;
    if (idx < C * M) {
        int c = idx / M;
        int m = idx - c * M;
        int which = m / O;
        int o = m - which * O;
        int qkv = which % 3;
        const float* w = (qkv == 0) ? wq : ((qkv == 1) ? wk : wv);
        float top = w[c * O + o];
        float bot = w[(C + c) * O + o];
        g_W[idx] = __float2half((which < 3) ? (top - bot) : bot);
    }
    if (idx < M) {
        int which = idx / O;
        int o = idx - which * O;
        float b = 0.f;
        if (which == 0) b = bq[o];
        else if (which == 1) b = bk[o];
        else if (which == 2) b = bv[o];
        g_B[idx] = b;
    }
}

// ---------------------------------------------------------------------------
// B-resident fp16 TC GEMM: g_T[N x M] = g_XH[N x K] @ g_W[K x M] + g_B
// Each CTA: one 128-col block, B tile (K x 128) resident in smem, loops over
// row tiles (stride gridDim.y), full A tile per iteration. 256 thr, 8 warps.
// ---------------------------------------------------------------------------
__device__ __forceinline__ uint32_t smem_u32(const void* p) {
    return (uint32_t)__cvta_generic_to_shared(p);
}
#define CP_ASYNC16(dst, src) \
    asm volatile("cp.async.cg.shared.global [%0], [%1], 16;" :: "r"(dst), "l"(src))
#define CP_COMMIT() asm volatile("cp.async.commit_group;" ::: "memory")
#define CP_WAIT0()  asm volatile("cp.async.wait_group 0;" :: : "memory")

template <int K>
__global__ __launch_bounds__(256) void gemm_v2_kernel(const __half* __restrict__ A,
                                                      int N, int M) {
    constexpr int AS = K + 8;    // A row stride (halfs)
    constexpr int BS = 136;      // B row stride (halfs)
    extern __shared__ __align__(16) char smem_raw[];
    __half* Asm = (__half*)smem_raw;                          // [128][AS]
    __half* Bsm = (__half*)(smem_raw + 128 * AS * 2);         // [K][BS]

    int tid  = threadIdx.x;
    int lane = tid & 31;
    int wid  = tid >> 5;
    int warp_m = wid >> 2;     // 0..1 -> 64 rows
    int warp_n = wid & 3;      // 0..3 -> 32 cols
    int col0 = blockIdx.x * 128;

    // ---- load B tile once (K x 128) ----
    {
        constexpr int CH = K * 128 / 8;      // 16B chunks
#pragma unroll
        for (int u = 0; u < CH / 256; u++) {
            int idx = tid + u * 256;
            int r   = idx >> 4;
            int c   = (idx & 15) << 3;
            CP_ASYNC16(smem_u32(&Bsm[r * BS + c]),
                       g_W + (size_t)r * M + col0 + c);
        }
        CP_COMMIT();
        CP_WAIT0();
        __syncthreads();
    }

    // bias for epilogue (depends only on cols)
    int g  = lane >> 2;
    int t4 = lane & 3;
    float bias_x[4], bias_y[4];
#pragma unroll
    for (int nt = 0; nt < 4; nt++) {
        int col = col0 + warp_n * 32 + nt * 8 + t4 * 2;
        bias_x[nt] = g_B[col];
        bias_y[nt] = g_B[col + 1];
    }

    int nTiles = (N + 127) >> 7;
    for (int rt = blockIdx.y; rt < nTiles; rt += gridDim.y) {
        int row0 = rt << 7;

        // ---- load full A tile (128 x K) ----
        constexpr int CHA = 128 * K / 8;
        constexpr int CPR = K / 8;           // chunks per row
#pragma unroll
        for (int u = 0; u < CHA / 256; u++) {
            int idx = tid + u * 256;
            int r   = idx / CPR;
            int c   = (idx % CPR) << 3;
            if (row0 + r < N) {
                CP_ASYNC16(smem_u32(&Asm[r * AS + c]),
                           A + (size_t)(row0 + r) * K + c);
            }
        }
        CP_COMMIT();
        CP_WAIT0();
        __syncthreads();

        float acc[4][4][4];
#pragma unroll
        for (int mt = 0; mt < 4; mt++)
#pragma unroll
            for (int nt = 0; nt < 4; nt++)
#pragma unroll
                for (int i = 0; i < 4; i++) acc[mt][nt][i] = 0.f;

        int m0 = warp_m * 64;
        int n0 = warp_n * 32;
#pragma unroll
        for (int kk = 0; kk < K; kk += 16) {
            uint32_t a[4][4];
#pragma unroll
            for (int mt = 0; mt < 4; mt++) {
                uint32_t addr = smem_u32(&Asm[(m0 + mt * 16 + (lane & 15)) * AS +
                                              kk + (lane >> 4) * 8]);
                asm volatile("ldmatrix.sync.aligned.m8n8.x4.shared.b16 {%0,%1,%2,%3}, [%4];"
                             : "=r"(a[mt][0]), "=r"(a[mt][1]), "=r"(a[mt][2]), "=r"(a[mt][3])
                             : "r"(addr));
            }
            uint32_t b[4][2];
#pragma unroll
            for (int np = 0; np < 2; np++) {
                uint32_t addr = smem_u32(&Bsm[(kk + (lane & 15)) * BS +
                                              n0 + np * 16 + (lane >> 4) * 8]);
                uint32_t r0, r1, r2, r3;
                asm volatile("ldmatrix.sync.aligned.m8n8.x4.trans.shared.b16 {%0,%1,%2,%3}, [%4];"
                             : "=r"(r0), "=r"(r1), "=r"(r2), "=r"(r3)
                             : "r"(addr));
                b[np * 2 + 0][0] = r0; b[np * 2 + 0][1] = r1;
                b[np * 2 + 1][0] = r2; b[np * 2 + 1][1] = r3;
            }
#pragma unroll
            for (int mt = 0; mt < 4; mt++)
#pragma unroll
                for (int nt = 0; nt < 4; nt++) {
                    asm volatile(
                        "mma.sync.aligned.m16n8k16.row.col.f32.f16.f16.f32 "
                        "{%0,%1,%2,%3}, {%4,%5,%6,%7}, {%8,%9}, {%0,%1,%2,%3};"
                        : "+f"(acc[mt][nt][0]), "+f"(acc[mt][nt][1]),
                          "+f"(acc[mt][nt][2]), "+f"(acc[mt][nt][3])
                        : "r"(a[mt][0]), "r"(a[mt][1]), "r"(a[mt][2]), "r"(a[mt][3]),
                          "r"(b[nt][0]), "r"(b[nt][1]));
                }
        }
        __syncthreads();   // all warps done reading Asm before next overwrite

        // ---- epilogue: + bias, fp16 store ----
#pragma unroll
        for (int mt = 0; mt < 4; mt++) {
#pragma unroll
            for (int nt = 0; nt < 4; nt++) {
                int col = col0 + warp_n * 32 + nt * 8 + t4 * 2;
#pragma unroll
                for (int h = 0; h < 2; h++) {
                    int r = row0 + warp_m * 64 + mt * 16 + g + h * 8;
                    if (r < N) {
                        __half2 o = __floats2half2_rn(acc[mt][nt][h * 2 + 0] + bias_x[nt],
                                                      acc[mt][nt][h * 2 + 1] + bias_y[nt]);
                        *(__half2*)(g_T + (size_t)r * M + col) = o;
                    }
                }
            }
        }
    }
}

// ---------------------------------------------------------------------------
// Aggregate: one warp per dst node, software-pipelined src loads.
//   MODE 0: X0 = relu(mean), XH = half(X0)   (O=128)
//   MODE 1: XH = half(relu(mean))            (O=64)
//   MODE 2: out = relu(mean + X0)            (O=128)
// ---------------------------------------------------------------------------
template <int O, int HS, int MODE>
__global__ __launch_bounds__(256) void agg_kernel(float* __restrict__ out, int N, int L) {
    int n = (blockIdx.x * 256 + threadIdx.x) >> 5;
    if (n >= N) return;
    int lane = threadIdx.x & 31;
    constexpr int V = O / 32;
    int base = lane * V;

    int cnt = g_CNT3[L * NN + n];
    float res[V];
#pragma unroll
    for (int u = 0; u < V; u++) res[u] = 0.f;

    if (cnt > 0) {
        constexpr int STRIDE = 6 * O;
        const int* srcs = g_SRCS3 + L * MAXE;
        const __half* D = g_T + (size_t)n * STRIDE;
        auto ld4 = [](const __half* p, float* o) {
            uint2 raw = *(const uint2*)p;
            __half2* h = (__half2*)&raw;
            float2 a = __half22float2(h[0]), b = __half22float2(h[1]);
            o[0] = a.x; o[1] = a.y; o[2] = b.x; o[3] = b.y;
        };
        auto ld2 = [](const __half* p, float* o) {
            float2 a = __half22float2(*(const __half2*)p);
            o[0] = a.x; o[1] = a.y;
        };
        float dq[V], dk[V], dv[V];
        if constexpr (V == 4) {
            ld4(D + base, dq); ld4(D + O + base, dk); ld4(D + 2 * O + base, dv);
        } else {
            ld2(D + base, dq); ld2(D + O + base, dk); ld2(D + 2 * O + base, dv);
        }

        const float scale = (HS == 16) ? 0.25f : 0.35355339059327373f;
        int off = g_OFF3[L * NN + n];
        int src = srcs[off];
        float sq[V], sk[V], sv[V];
        {
            const __half* S = g_T + (size_t)src * STRIDE + 3 * O;
            if constexpr (V == 4) {
                ld4(S + base, sq); ld4(S + O + base, sk); ld4(S + 2 * O + base, sv);
            } else {
                ld2(S + base, sq); ld2(S + O + base, sk); ld2(S + 2 * O + base, sv);
            }
        }
        for (int j = 0; j < cnt; j++) {
            // prefetch next edge's src half before computing current
            int nsrc = (j + 1 < cnt) ? srcs[off + j + 1] : src;
            const __half* NS = g_T + (size_t)nsrc * STRIDE + 3 * O;
            float nq[V], nk[V], nv[V];
            if constexpr (V == 4) {
                ld4(NS + base, nq); ld4(NS + O + base, nk); ld4(NS + 2 * O + base, nv);
            } else {
                ld2(NS + base, nq); ld2(NS + O + base, nk); ld2(NS + 2 * O + base, nv);
            }

            int dd = n - src;
            if (dd < 0) dd = -dd;
            float ew = (dd > 8) ? 1.0f : ((dd == 8) ? 0.0f : -1.0f);

            float p[V];
            float ssum = 0.f;
#pragma unroll
            for (int u = 0; u < V; u++) {
                float t = (dq[u] + sq[u]) * (dk[u] + sk[u]) * scale;
                p[u] = __expf(t);
                ssum += p[u];
            }
            ssum += __shfl_xor_sync(0xffffffffu, ssum, 1);
            ssum += __shfl_xor_sync(0xffffffffu, ssum, 2);
            float w = __fdividef(ew, ssum);
#pragma unroll
            for (int u = 0; u < V; u++)
                res[u] = fmaf(p[u] * (dv[u] + sv[u]), w, res[u]);

            // rotate
#pragma unroll
            for (int u = 0; u < V; u++) { sq[u] = nq[u]; sk[u] = nk[u]; sv[u] = nv[u]; }
            src = nsrc;
        }
        float invc = __fdividef(1.0f, (float)cnt);
#pragma unroll
        for (int u = 0; u < V; u++) res[u] *= invc;
    }

    if constexpr (MODE == 0) {
        float v[4];
#pragma unroll
        for (int u = 0; u < 4; u++) v[u] = fmaxf(res[u], 0.f);
        *(float4*)(g_X0 + (size_t)n * 128 + base) = make_float4(v[0], v[1], v[2], v[3]);
        __half2 h[2];
        h[0] = __floats2half2_rn(v[0], v[1]);
        h[1] = __floats2half2_rn(v[2], v[3]);
        *(uint2*)(g_XH + (size_t)n * 128 + base) = *(uint2*)h;
    } else if constexpr (MODE == 1) {
        __half2 h = __floats2half2_rn(fmaxf(res[0], 0.f), fmaxf(res[1], 0.f));
        *(__half2*)(g_XH + (size_t)n * 64 + base) = h;
    } else {
        float4 x0 = *(const float4*)(g_X0 + (size_t)n * 128 + base);
        float4 o;
        o.x = fmaxf(res[0] + x0.x, 0.f);
        o.y = fmaxf(res[1] + x0.y, 0.f);
        o.z = fmaxf(res[2] + x0.z, 0.f);
        o.w = fmaxf(res[3] + x0.w, 0.f);
        *(float4*)(out + (size_t)n * 128 + base) = o;
    }
}

// ---------------------------------------------------------------------------
extern "C" void kernel_launch(void* const* d_in, const int* in_sizes, int n_in,
                              void* d_out, int out_size) {
    const float* x   = (const float*)d_in[0];
    const int*   e0  = (const int*)d_in[1];
    const int*   e1  = (const int*)d_in[2];
    const int*   e2  = (const int*)d_in[3];
    // d_in[4] = batch (unused)
    const float* wq0 = (const float*)d_in[5],  *bq0 = (const float*)d_in[6];
    const float* wk0 = (const float*)d_in[7],  *bk0 = (const float*)d_in[8];
    const float* wv0 = (const float*)d_in[9],  *bv0 = (const float*)d_in[10];
    const float* wq1 = (const float*)d_in[11], *bq1 = (const float*)d_in[12];
    const float* wk1 = (const float*)d_in[13], *bk1 = (const float*)d_in[14];
    const float* wv1 = (const float*)d_in[15], *bv1 = (const float*)d_in[16];
    const float* wq2 = (const float*)d_in[17], *bq2 = (const float*)d_in[18];
    const float* wk2 = (const float*)d_in[19], *bk2 = (const float*)d_in[20];
    const float* wv2 = (const float*)d_in[21], *bv2 = (const float*)d_in[22];
    float* out = (float*)d_out;

    int N  = in_sizes[0] / 128;   // 50000
    int E  = in_sizes[1] / 2;     // 500000 (all three lists equal length)

    __half* pXH = nullptr;
    cudaGetSymbolAddress((void**)&pXH, g_XH);

    static bool attr_set = false;
    if (!attr_set) {
        cudaFuncSetAttribute(gemm_v2_kernel<128>,
                             cudaFuncAttributeMaxDynamicSharedMemorySize, 128 * 136 * 2 * 2);
        cudaFuncSetAttribute(gemm_v2_kernel<64>,
                             cudaFuncAttributeMaxDynamicSharedMemorySize,
                             128 * 72 * 2 + 64 * 136 * 2);
        attr_set = true;
    }

    // ---- up-front: x conversion + batched edge sorts (layer-independent) ----
    convert_x_kernel<<<(N * 128 + 255) / 256, 256>>>(x, N * 128);
    zero3_kernel<<<(3 * NN + 255) / 256, 256>>>();
    {
        dim3 ge((E + 255) / 256, 3);
        dim3 gn((NN + 255) / 256, 3);
        hist3_kernel<<<ge, 256>>>(e0, e1, e2, E);
        scan1_kernel<<<gn, 256>>>();
        scan2_kernel<<<dim3(1, 3), 256>>>((NN + 255) / 256);
        scan3_kernel<<<gn, 256>>>();
        scatter3_kernel<<<ge, 256>>>(e0, e1, e2, E);
    }

    int aggGrid = (N * 32 + 255) / 256;

    // ---- Layer 0: C=128, O=128, M=768 ----
    {
        const int C = 128, O = 128, M = 6 * O;
        build_w_kernel<<<(C * M + 255) / 256, 256>>>(wq0, wk0, wv0, bq0, bk0, bv0, C, O);
        dim3 grid(M / 128, 49);
        gemm_v2_kernel<128><<<grid, 256, 128 * 136 * 2 * 2>>>(pXH, N, M);
        agg_kernel<128, 16, 0><<<aggGrid, 256>>>(nullptr, N, 0);
    }
    // ---- Layer 1: C=128, O=64, M=384 ----
    {
        const int C = 128, O = 64, M = 6 * O;
        build_w_kernel<<<(C * M + 255) / 256, 256>>>(wq1, wk1, wv1, bq1, bk1, bv1, C, O);
        dim3 grid(M / 128, 98);
        gemm_v2_kernel<128><<<grid, 256, 128 * 136 * 2 * 2>>>(pXH, N, M);
        agg_kernel<64, 8, 1><<<aggGrid, 256>>>(nullptr, N, 1);
    }
    // ---- Layer 2: C=64, O=128, M=768 ----
    {
        const int C = 64, O = 128, M = 6 * O;
        build_w_kernel<<<(C * M + 255) / 256, 256>>>(wq2, wk2, wv2, bq2, bk2, bv2, C, O);
        dim3 grid(M / 128, 49);
        gemm_v2_kernel<64><<<grid, 256, 128 * 72 * 2 + 64 * 136 * 2>>>(pXH, N, M);
        agg_kernel<128, 16, 2><<<aggGrid, 256>>>(out, N, 2);
    }
}

// round 10
// speedup vs baseline: 2.9345x; 1.1146x over previous
#include <cuda_runtime.h>
#include <cuda_fp16.h>
#include <cstdint>
#include <cstddef>

// ---------------------------------------------------------------------------
// EdgeConvEncoder: 3-layer EdgeConv GNN.
//   side stream: batched counting sort of all 3 edge lists by dst (forked)
//   main stream: convert x, build all W, per-layer B-resident double-buffered
//                fp16 TC GEMM + warp-per-node aggregation (fused finalize).
// ---------------------------------------------------------------------------

#define NN 50000
#define MAXE 500000

__device__ __half g_T[NN * 768];        // node tables (fp16), max 6*O cols
__device__ int    g_CNT3[3 * NN];       // per-layer histograms
__device__ int    g_OFF3[3 * NN];       // per-layer exclusive scans
__device__ int    g_POS3[3 * NN];       // scatter cursors
__device__ int    g_PART3[3 * 256];     // scan partials
__device__ int    g_SRCS3[3 * MAXE];    // src ids sorted by dst, per layer
__device__ float  g_X0[NN * 128];       // layer-0 output fp32 (residual)
__device__ __half g_XH[NN * 128];       // current GEMM input (fp16)
__device__ __half g_W3[3][128 * 768];   // combined weights per layer
__device__ float  g_B3[3][768];         // combined bias rows per layer

// ---------------------------------------------------------------------------
__global__ void convert_x_kernel(const float* __restrict__ x, int n) {
    int i = blockIdx.x * blockDim.x + threadIdx.x;
    if (i < n) g_XH[i] = __float2half(x[i]);
}

__global__ void zero3_kernel() {
    int i = blockIdx.x * blockDim.x + threadIdx.x;
    if (i < 3 * NN) g_CNT3[i] = 0;
}

// ---------------------------------------------------------------------------
// Batched counting sort (blockIdx.y = layer).
// ---------------------------------------------------------------------------
__global__ void hist3_kernel(const int* __restrict__ e0, const int* __restrict__ e1,
                             const int* __restrict__ e2, int E) {
    int L = blockIdx.y;
    const int* e = (L == 0) ? e0 : ((L == 1) ? e1 : e2);
    int i = blockIdx.x * blockDim.x + threadIdx.x;
    if (i < E) atomicAdd(&g_CNT3[L * NN + e[E + i]], 1);
}

__global__ void scan1_kernel() {
    int L = blockIdx.y;
    __shared__ int s[256];
    int t = threadIdx.x;
    int i = blockIdx.x * 256 + t;
    int v = (i < NN) ? g_CNT3[L * NN + i] : 0;
    s[t] = v;
    __syncthreads();
#pragma unroll
    for (int d = 1; d < 256; d <<= 1) {
        int x = (t >= d) ? s[t - d] : 0;
        __syncthreads();
        s[t] += x;
        __syncthreads();
    }
    if (i < NN) g_OFF3[L * NN + i] = s[t] - v;
    if (t == 255) g_PART3[L * 256 + blockIdx.x] = s[255];
}

__global__ void scan2_kernel(int P) {
    int L = blockIdx.y;
    __shared__ int s[256];
    int t = threadIdx.x;
    int v = (t < P) ? g_PART3[L * 256 + t] : 0;
    s[t] = v;
    __syncthreads();
#pragma unroll
    for (int d = 1; d < 256; d <<= 1) {
        int x = (t >= d) ? s[t - d] : 0;
        __syncthreads();
        s[t] += x;
        __syncthreads();
    }
    if (t < P) g_PART3[L * 256 + t] = s[t] - v;
}

__global__ void scan3_kernel() {
    int L = blockIdx.y;
    int i = blockIdx.x * 256 + threadIdx.x;
    if (i < NN) {
        int o = g_OFF3[L * NN + i] + g_PART3[L * 256 + blockIdx.x];
        g_OFF3[L * NN + i] = o;
        g_POS3[L * NN + i] = o;
    }
}

__global__ void scatter3_kernel(const int* __restrict__ e0, const int* __restrict__ e1,
                                const int* __restrict__ e2, int E) {
    int L = blockIdx.y;
    const int* e = (L == 0) ? e0 : ((L == 1) ? e1 : e2);
    int i = blockIdx.x * blockDim.x + threadIdx.x;
    if (i < E) {
        int src = e[i];
        int dst = e[E + i];
        int pos = atomicAdd(&g_POS3[L * NN + dst], 1);
        g_SRCS3[L * MAXE + pos] = src;
    }
}

// ---------------------------------------------------------------------------
// Build combined fp16 weight matrix for layer L:
// cols [0,O)=wq_top-wq_bot [O,2O)=wk diff [2O,3O)=wv diff
// cols [3O,4O)=wq_bot      [4O,5O)=wk_bot [5O,6O)=wv_bot
// ---------------------------------------------------------------------------
__global__ void build_w_kernel(const float* __restrict__ wq, const float* __restrict__ wk,
                               const float* __restrict__ wv, const float* __restrict__ bq,
                               const float* __restrict__ bk, const float* __restrict__ bv,
                               int C, int O, int L) {
    int M = 6 * O;
    int idx = blockIdx.x * blockDim.x + threadIdx.x;
    if (idx < C * M) {
        int c = idx / M;
        int m = idx - c * M;
        int which = m / O;
        int o = m - which * O;
        int qkv = which % 3;
        const float* w = (qkv == 0) ? wq : ((qkv == 1) ? wk : wv);
        float top = w[c * O + o];
        float bot = w[(C + c) * O + o];
        g_W3[L][idx] = __float2half((which < 3) ? (top - bot) : bot);
    }
    if (idx < M) {
        int which = idx / O;
        int o = idx - which * O;
        float b = 0.f;
        if (which == 0) b = bq[o];
        else if (which == 1) b = bk[o];
        else if (which == 2) b = bv[o];
        g_B3[L][idx] = b;
    }
}

// ---------------------------------------------------------------------------
// B-resident + A double-buffered fp16 TC GEMM:
//   g_T[N x M] = g_XH[N x K] @ g_W3[L][K x M] + g_B3[L]
// Each CTA owns one 128-col block; B tile (K x 128) resident in smem;
// loops over 128-row tiles with 2-stage cp.async on A.
// ---------------------------------------------------------------------------
__device__ __forceinline__ uint32_t smem_u32(const void* p) {
    return (uint32_t)__cvta_generic_to_shared(p);
}
#define CP_ASYNC16(dst, src) \
    asm volatile("cp.async.cg.shared.global [%0], [%1], 16;" :: "r"(dst), "l"(src))
#define CP_COMMIT() asm volatile("cp.async.commit_group;" ::: "memory")
#define CP_WAIT(n)  asm volatile("cp.async.wait_group %0;" :: "n"(n) : "memory")

template <int K>
__global__ __launch_bounds__(256) void gemm_v3_kernel(const __half* __restrict__ A,
                                                      int N, int M, int L) {
    constexpr int AS = K + 8;    // A row stride (halfs)
    constexpr int BS = 136;      // B row stride (halfs)
    extern __shared__ __align__(16) char smem_raw[];
    __half* Asm0 = (__half*)smem_raw;                          // [128][AS]
    __half* Asm1 = (__half*)(smem_raw + 128 * AS * 2);         // [128][AS]
    __half* Bsm  = (__half*)(smem_raw + 2 * 128 * AS * 2);     // [K][BS]

    int tid  = threadIdx.x;
    int lane = tid & 31;
    int wid  = tid >> 5;
    int warp_m = wid >> 2;     // 0..1 -> 64 rows
    int warp_n = wid & 3;      // 0..3 -> 32 cols
    int col0 = blockIdx.x * 128;
    const __half* W = g_W3[L];

    // ---- load B tile once (K x 128) ----
    {
        constexpr int CH = K * 128 / 8;      // 16B chunks
#pragma unroll
        for (int u = 0; u < CH / 256; u++) {
            int idx = tid + u * 256;
            int r   = idx >> 4;
            int c   = (idx & 15) << 3;
            CP_ASYNC16(smem_u32(&Bsm[r * BS + c]),
                       W + (size_t)r * M + col0 + c);
        }
        CP_COMMIT();
    }

    // bias for epilogue
    int g  = lane >> 2;
    int t4 = lane & 3;
    float bias_x[4], bias_y[4];
#pragma unroll
    for (int nt = 0; nt < 4; nt++) {
        int col = col0 + warp_n * 32 + nt * 8 + t4 * 2;
        bias_x[nt] = g_B3[L][col];
        bias_y[nt] = g_B3[L][col + 1];
    }

    auto load_a = [&](__half* dst, int rt) {
        int row0 = rt << 7;
        constexpr int CHA = 128 * K / 8;
        constexpr int CPR = K / 8;
#pragma unroll
        for (int u = 0; u < CHA / 256; u++) {
            int idx = tid + u * 256;
            int r   = idx / CPR;
            int c   = (idx % CPR) << 3;
            if (row0 + r < N) {
                CP_ASYNC16(smem_u32(&dst[r * AS + c]),
                           A + (size_t)(row0 + r) * K + c);
            }
        }
        CP_COMMIT();
    };

    int nTiles = (N + 127) >> 7;
    int rt0 = blockIdx.y;
    if (rt0 >= nTiles) return;
    load_a(Asm0, rt0);

    int it = 0;
    for (int rt = rt0; rt < nTiles; rt += gridDim.y, it++) {
        __half* Acur = (it & 1) ? Asm1 : Asm0;
        __half* Anxt = (it & 1) ? Asm0 : Asm1;
        int rtn = rt + gridDim.y;
        if (rtn < nTiles) {
            load_a(Anxt, rtn);
            CP_WAIT(1);        // wait for Acur (+B on first iter)
        } else {
            CP_WAIT(0);
        }
        __syncthreads();

        int row0 = rt << 7;
        float acc[4][4][4];
#pragma unroll
        for (int mt = 0; mt < 4; mt++)
#pragma unroll
            for (int nt = 0; nt < 4; nt++)
#pragma unroll
                for (int i = 0; i < 4; i++) acc[mt][nt][i] = 0.f;

        int m0 = warp_m * 64;
        int n0 = warp_n * 32;
#pragma unroll
        for (int kk = 0; kk < K; kk += 16) {
            uint32_t a[4][4];
#pragma unroll
            for (int mt = 0; mt < 4; mt++) {
                uint32_t addr = smem_u32(&Acur[(m0 + mt * 16 + (lane & 15)) * AS +
                                               kk + (lane >> 4) * 8]);
                asm volatile("ldmatrix.sync.aligned.m8n8.x4.shared.b16 {%0,%1,%2,%3}, [%4];"
                             : "=r"(a[mt][0]), "=r"(a[mt][1]), "=r"(a[mt][2]), "=r"(a[mt][3])
                             : "r"(addr));
            }
            uint32_t b[4][2];
#pragma unroll
            for (int np = 0; np < 2; np++) {
                uint32_t addr = smem_u32(&Bsm[(kk + (lane & 15)) * BS +
                                              n0 + np * 16 + (lane >> 4) * 8]);
                uint32_t r0, r1, r2, r3;
                asm volatile("ldmatrix.sync.aligned.m8n8.x4.trans.shared.b16 {%0,%1,%2,%3}, [%4];"
                             : "=r"(r0), "=r"(r1), "=r"(r2), "=r"(r3)
                             : "r"(addr));
                b[np * 2 + 0][0] = r0; b[np * 2 + 0][1] = r1;
                b[np * 2 + 1][0] = r2; b[np * 2 + 1][1] = r3;
            }
#pragma unroll
            for (int mt = 0; mt < 4; mt++)
#pragma unroll
                for (int nt = 0; nt < 4; nt++) {
                    asm volatile(
                        "mma.sync.aligned.m16n8k16.row.col.f32.f16.f16.f32 "
                        "{%0,%1,%2,%3}, {%4,%5,%6,%7}, {%8,%9}, {%0,%1,%2,%3};"
                        : "+f"(acc[mt][nt][0]), "+f"(acc[mt][nt][1]),
                          "+f"(acc[mt][nt][2]), "+f"(acc[mt][nt][3])
                        : "r"(a[mt][0]), "r"(a[mt][1]), "r"(a[mt][2]), "r"(a[mt][3]),
                          "r"(b[nt][0]), "r"(b[nt][1]));
                }
        }

        // ---- epilogue: + bias, fp16 store ----
#pragma unroll
        for (int mt = 0; mt < 4; mt++) {
#pragma unroll
            for (int nt = 0; nt < 4; nt++) {
                int col = col0 + warp_n * 32 + nt * 8 + t4 * 2;
#pragma unroll
                for (int h = 0; h < 2; h++) {
                    int r = row0 + warp_m * 64 + mt * 16 + g + h * 8;
                    if (r < N) {
                        __half2 o = __floats2half2_rn(acc[mt][nt][h * 2 + 0] + bias_x[nt],
                                                      acc[mt][nt][h * 2 + 1] + bias_y[nt]);
                        *(__half2*)(g_T + (size_t)r * M + col) = o;
                    }
                }
            }
        }
        __syncthreads();   // all warps done with Acur before it is refilled
    }
}

// ---------------------------------------------------------------------------
// Aggregate: one warp per dst node, 2-edge unroll for MLP.
//   MODE 0: X0 = relu(mean), XH = half(X0)   (O=128)
//   MODE 1: XH = half(relu(mean))            (O=64)
//   MODE 2: out = relu(mean + X0)            (O=128)
// ---------------------------------------------------------------------------
template <int O, int HS, int MODE>
__global__ __launch_bounds__(256) void agg_kernel(float* __restrict__ out, int N, int L) {
    int n = (blockIdx.x * 256 + threadIdx.x) >> 5;
    if (n >= N) return;
    int lane = threadIdx.x & 31;
    constexpr int V = O / 32;
    int base = lane * V;

    int cnt = g_CNT3[L * NN + n];
    float res[V];
#pragma unroll
    for (int u = 0; u < V; u++) res[u] = 0.f;

    if (cnt > 0) {
        constexpr int STRIDE = 6 * O;
        const int* srcs = g_SRCS3 + L * MAXE;
        const __half* D = g_T + (size_t)n * STRIDE;
        auto ld4 = [](const __half* p, float* o) {
            uint2 raw = *(const uint2*)p;
            __half2* h = (__half2*)&raw;
            float2 a = __half22float2(h[0]), b = __half22float2(h[1]);
            o[0] = a.x; o[1] = a.y; o[2] = b.x; o[3] = b.y;
        };
        auto ld2 = [](const __half* p, float* o) {
            float2 a = __half22float2(*(const __half2*)p);
            o[0] = a.x; o[1] = a.y;
        };
        float dq[V], dk[V], dv[V];
        if constexpr (V == 4) {
            ld4(D + base, dq); ld4(D + O + base, dk); ld4(D + 2 * O + base, dv);
        } else {
            ld2(D + base, dq); ld2(D + O + base, dk); ld2(D + 2 * O + base, dv);
        }

        const float scale = (HS == 16) ? 0.25f : 0.35355339059327373f;
        int off = g_OFF3[L * NN + n];

        auto edge_contrib = [&](int src, const float* sq, const float* sk,
                                const float* sv) {
            int dd = n - src;
            if (dd < 0) dd = -dd;
            float ew = (dd > 8) ? 1.0f : ((dd == 8) ? 0.0f : -1.0f);
            float p[V];
            float ssum = 0.f;
#pragma unroll
            for (int u = 0; u < V; u++) {
                float t = (dq[u] + sq[u]) * (dk[u] + sk[u]) * scale;
                p[u] = __expf(t);
                ssum += p[u];
            }
            ssum += __shfl_xor_sync(0xffffffffu, ssum, 1);
            ssum += __shfl_xor_sync(0xffffffffu, ssum, 2);
            float w = __fdividef(ew, ssum);
#pragma unroll
            for (int u = 0; u < V; u++)
                res[u] = fmaf(p[u] * (dv[u] + sv[u]), w, res[u]);
        };

        int j = 0;
        for (; j + 2 <= cnt; j += 2) {
            int s0 = srcs[off + j];
            int s1 = srcs[off + j + 1];
            const __half* S0 = g_T + (size_t)s0 * STRIDE + 3 * O;
            const __half* S1 = g_T + (size_t)s1 * STRIDE + 3 * O;
            float aq[V], ak[V], av[V], bq[V], bk[V], bv[V];
            if constexpr (V == 4) {
                ld4(S0 + base, aq); ld4(S0 + O + base, ak); ld4(S0 + 2 * O + base, av);
                ld4(S1 + base, bq); ld4(S1 + O + base, bk); ld4(S1 + 2 * O + base, bv);
            } else {
                ld2(S0 + base, aq); ld2(S0 + O + base, ak); ld2(S0 + 2 * O + base, av);
                ld2(S1 + base, bq); ld2(S1 + O + base, bk); ld2(S1 + 2 * O + base, bv);
            }
            edge_contrib(s0, aq, ak, av);
            edge_contrib(s1, bq, bk, bv);
        }
        if (j < cnt) {
            int s0 = srcs[off + j];
            const __half* S0 = g_T + (size_t)s0 * STRIDE + 3 * O;
            float aq[V], ak[V], av[V];
            if constexpr (V == 4) {
                ld4(S0 + base, aq); ld4(S0 + O + base, ak); ld4(S0 + 2 * O + base, av);
            } else {
                ld2(S0 + base, aq); ld2(S0 + O + base, ak); ld2(S0 + 2 * O + base, av);
            }
            edge_contrib(s0, aq, ak, av);
        }
        float invc = __fdividef(1.0f, (float)cnt);
#pragma unroll
        for (int u = 0; u < V; u++) res[u] *= invc;
    }

    if constexpr (MODE == 0) {
        float v[4];
#pragma unroll
        for (int u = 0; u < 4; u++) v[u] = fmaxf(res[u], 0.f);
        *(float4*)(g_X0 + (size_t)n * 128 + base) = make_float4(v[0], v[1], v[2], v[3]);
        __half2 h[2];
        h[0] = __floats2half2_rn(v[0], v[1]);
        h[1] = __floats2half2_rn(v[2], v[3]);
        *(uint2*)(g_XH + (size_t)n * 128 + base) = *(uint2*)h;
    } else if constexpr (MODE == 1) {
        __half2 h = __floats2half2_rn(fmaxf(res[0], 0.f), fmaxf(res[1], 0.f));
        *(__half2*)(g_XH + (size_t)n * 64 + base) = h;
    } else {
        float4 x0 = *(const float4*)(g_X0 + (size_t)n * 128 + base);
        float4 o;
        o.x = fmaxf(res[0] + x0.x, 0.f);
        o.y = fmaxf(res[1] + x0.y, 0.f);
        o.z = fmaxf(res[2] + x0.z, 0.f);
        o.w = fmaxf(res[3] + x0.w, 0.f);
        *(float4*)(out + (size_t)n * 128 + base) = o;
    }
}

// ---------------------------------------------------------------------------
extern "C" void kernel_launch(void* const* d_in, const int* in_sizes, int n_in,
                              void* d_out, int out_size) {
    const float* x   = (const float*)d_in[0];
    const int*   e0  = (const int*)d_in[1];
    const int*   e1  = (const int*)d_in[2];
    const int*   e2  = (const int*)d_in[3];
    // d_in[4] = batch (unused)
    const float* wq0 = (const float*)d_in[5],  *bq0 = (const float*)d_in[6];
    const float* wk0 = (const float*)d_in[7],  *bk0 = (const float*)d_in[8];
    const float* wv0 = (const float*)d_in[9],  *bv0 = (const float*)d_in[10];
    const float* wq1 = (const float*)d_in[11], *bq1 = (const float*)d_in[12];
    const float* wk1 = (const float*)d_in[13], *bk1 = (const float*)d_in[14];
    const float* wv1 = (const float*)d_in[15], *bv1 = (const float*)d_in[16];
    const float* wq2 = (const float*)d_in[17], *bq2 = (const float*)d_in[18];
    const float* wk2 = (const float*)d_in[19], *bk2 = (const float*)d_in[20];
    const float* wv2 = (const float*)d_in[21], *bv2 = (const float*)d_in[22];
    float* out = (float*)d_out;

    int N  = in_sizes[0] / 128;   // 50000
    int E  = in_sizes[1] / 2;     // 500000

    __half* pXH = nullptr;
    cudaGetSymbolAddress((void**)&pXH, g_XH);

    constexpr int SMEM128 = 2 * 128 * 136 * 2 + 128 * 136 * 2;  // 104448
    constexpr int SMEM64  = 2 * 128 * 72 * 2  + 64 * 136 * 2;   // 54272

    static cudaStream_t s2 = nullptr;
    static cudaEvent_t evFork = nullptr, evJoin = nullptr;
    if (s2 == nullptr) {
        cudaFuncSetAttribute(gemm_v3_kernel<128>,
                             cudaFuncAttributeMaxDynamicSharedMemorySize, SMEM128);
        cudaFuncSetAttribute(gemm_v3_kernel<64>,
                             cudaFuncAttributeMaxDynamicSharedMemorySize, SMEM64);
        cudaStreamCreateWithFlags(&s2, cudaStreamNonBlocking);
        cudaEventCreateWithFlags(&evFork, cudaEventDisableTiming);
        cudaEventCreateWithFlags(&evJoin, cudaEventDisableTiming);
    }

    // ---- fork: edge sorts on side stream, concurrent with GEMM L0 path ----
    cudaEventRecord(evFork, 0);
    cudaStreamWaitEvent(s2, evFork, 0);
    {
        dim3 ge((E + 255) / 256, 3);
        dim3 gn((NN + 255) / 256, 3);
        zero3_kernel<<<(3 * NN + 255) / 256, 256, 0, s2>>>();
        hist3_kernel<<<ge, 256, 0, s2>>>(e0, e1, e2, E);
        scan1_kernel<<<gn, 256, 0, s2>>>();
        scan2_kernel<<<dim3(1, 3), 256, 0, s2>>>((NN + 255) / 256);
        scan3_kernel<<<gn, 256, 0, s2>>>();
        scatter3_kernel<<<ge, 256, 0, s2>>>(e0, e1, e2, E);
    }
    cudaEventRecord(evJoin, s2);

    // ---- main stream: convert + build all weights + GEMM L0 ----
    convert_x_kernel<<<(N * 128 + 255) / 256, 256>>>(x, N * 128);
    build_w_kernel<<<(128 * 768 + 255) / 256, 256>>>(wq0, wk0, wv0, bq0, bk0, bv0, 128, 128, 0);
    build_w_kernel<<<(128 * 384 + 255) / 256, 256>>>(wq1, wk1, wv1, bq1, bk1, bv1, 128, 64, 1);
    build_w_kernel<<<(64 * 768 + 255) / 256, 256>>>(wq2, wk2, wv2, bq2, bk2, bv2, 64, 128, 2);

    int aggGrid = (N * 32 + 255) / 256;

    // ---- Layer 0: C=128, O=128, M=768 ----
    gemm_v3_kernel<128><<<dim3(6, 49), 256, SMEM128>>>(pXH, N, 768, 0);
    cudaStreamWaitEvent(0, evJoin, 0);   // sorts must be done before agg
    agg_kernel<128, 16, 0><<<aggGrid, 256>>>(nullptr, N, 0);

    // ---- Layer 1: C=128, O=64, M=384 ----
    gemm_v3_kernel<128><<<dim3(3, 98), 256, SMEM128>>>(pXH, N, 384, 1);
    agg_kernel<64, 8, 1><<<aggGrid, 256>>>(nullptr, N, 1);

    // ---- Layer 2: C=64, O=128, M=768 ----
    gemm_v3_kernel<64><<<dim3(6, 49), 256, SMEM64>>>(pXH, N, 768, 2);
    agg_kernel<128, 16, 2><<<aggGrid, 256>>>(out, N, 2);
}